// round 12
// baseline (speedup 1.0000x reference)
#include <cuda_runtime.h>
#include <cuda_bf16.h>
#include <cuda_fp16.h>
#include <cstdint>

#define B_N   2048
#define D_N   1024
#define S_N   30720
#define SN4   7680
#define NTHR  524288
#define KTOP  131072u
#define KAUX  2097152u
#define TOPCAP 160
#define AUXCAP 2048
#define BANDCAP 16384
#define CANDCAP (4u<<20)
#define NOFF  23040   /* tensor cols [0,NOFF), fma cols [NOFF,S_N) */

/* ------------------------- scratch ------------------------- */
__device__ float g_acts[(size_t)B_N * S_N];
__device__ float g_xc[B_N * D_N];
__device__ float g_recon[B_N * D_N];
__device__ unsigned g_hist_a[4096];
__device__ unsigned g_hist_d[4096];
__device__ unsigned char g_dead[S_N];
__device__ int g_any_dead;
__device__ unsigned g_cand_a[CANDCAP];
__device__ unsigned g_cand_d[CANDCAP];
__device__ int g_nca, g_ncd;
__device__ int g_b1a, g_b1d, g_b2a, g_b2d;
__device__ unsigned g_r1a, g_r1d;
__device__ unsigned g_tba, g_tbd;
__device__ unsigned g_hib, g_lob;
__device__ int g_bidx[BANDCAP];
__device__ float g_bhi[BANDCAP], g_blo[BANDCAP];
__device__ int g_nband, g_nhi;
__device__ unsigned short g_tcol[B_N * TOPCAP];
__device__ float          g_tval[B_N * TOPCAP];
__device__ int            g_tcnt[B_N];
__device__ unsigned short g_acol[(size_t)B_N * AUXCAP];
__device__ float          g_aval[(size_t)B_N * AUXCAP];
__device__ int            g_acnt[B_N];
__device__ double g_l2s[4];
__device__ double g_l1s;
__device__ unsigned long long g_l0s;
__device__ double g_auxs;

/* encoder fp16 GEMM scratch */
__device__ __half g_xhi[B_N * D_N];
__device__ __half g_Whi[(size_t)S_N * D_N];          /* W_enc^T fp16 [n][k] */
__device__ float  g_WTe[(size_t)S_N * D_N];          /* W_enc^T exact f32 [n][k] */

/* dense aux GEMM scratch */
__device__ __nv_bfloat16 g_A[(size_t)B_N * S_N];
__device__ __nv_bfloat16 g_WT[(size_t)D_N * S_N];
__device__ int g_dmap[S_N];
__device__ int g_dinv[S_N];
__device__ int g_dcnt[32];
__device__ int g_ndead, g_ndead_pad;

/* ------------------------- exact f32 helpers ------------------------- */
__device__ __forceinline__ float fadd_rn(float a, float b) {
    float r; asm("add.rn.f32 %0, %1, %2;" : "=f"(r) : "f"(a), "f"(b)); return r;
}
__device__ __forceinline__ float fsub_rn(float a, float b) {
    float r; asm("sub.rn.f32 %0, %1, %2;" : "=f"(r) : "f"(a), "f"(b)); return r;
}
__device__ __forceinline__ float fmul_rn(float a, float b) {
    float r; asm("mul.rn.f32 %0, %1, %2;" : "=f"(r) : "f"(a), "f"(b)); return r;
}
__device__ __forceinline__ float ffma_rn(float a, float b, float c) {
    float r; asm("fma.rn.f32 %0, %1, %2, %3;" : "=f"(r) : "f"(a), "f"(b), "f"(c)); return r;
}

/* f32x2 helpers (fma pipe) */
__device__ __forceinline__ void ffma2(unsigned long long &c,
                                      unsigned long long a,
                                      unsigned long long b) {
    asm("fma.rn.f32x2 %0, %1, %2, %0;" : "+l"(c) : "l"(a), "l"(b));
}
__device__ __forceinline__ unsigned long long dup2(float a) {
    unsigned long long r;
    asm("mov.b64 %0, {%1, %1};" : "=l"(r) : "f"(a));
    return r;
}
__device__ __forceinline__ unsigned long long pk2(float x, float y) {
    unsigned long long r;
    asm("mov.b64 %0, {%1, %2};" : "=l"(r) : "f"(x), "f"(y));
    return r;
}
__device__ __forceinline__ float2 upk(unsigned long long v) {
    float2 r;
    asm("mov.b64 {%0, %1}, %2;" : "=f"(r.x), "=f"(r.y) : "l"(v));
    return r;
}

/* mma.sync bf16 / fp16 (baseline PTX, plain sm_103) */
__device__ __forceinline__ void mma_bf16(float* c, const unsigned* a, const unsigned* b) {
    asm volatile(
        "mma.sync.aligned.m16n8k16.row.col.f32.bf16.bf16.f32 "
        "{%0,%1,%2,%3}, {%4,%5,%6,%7}, {%8,%9}, {%0,%1,%2,%3};"
        : "+f"(c[0]), "+f"(c[1]), "+f"(c[2]), "+f"(c[3])
        : "r"(a[0]), "r"(a[1]), "r"(a[2]), "r"(a[3]), "r"(b[0]), "r"(b[1]));
}
__device__ __forceinline__ void mma_fp16(float* c, const unsigned* a, const unsigned* b) {
    asm volatile(
        "mma.sync.aligned.m16n8k16.row.col.f32.f16.f16.f32 "
        "{%0,%1,%2,%3}, {%4,%5,%6,%7}, {%8,%9}, {%0,%1,%2,%3};"
        : "+f"(c[0]), "+f"(c[1]), "+f"(c[2]), "+f"(c[3])
        : "r"(a[0]), "r"(a[1]), "r"(a[2]), "r"(a[3]), "r"(b[0]), "r"(b[1]));
}
__device__ __forceinline__ uint32_t smem_u32(const void* p) {
    uint32_t a;
    asm("{ .reg .u64 t; cvta.to.shared.u64 t, %1; cvt.u32.u64 %0, t; }"
        : "=r"(a) : "l"(p));
    return a;
}
__device__ __forceinline__ void ldm4(unsigned &r0, unsigned &r1,
                                     unsigned &r2, unsigned &r3, unsigned addr) {
    asm volatile("ldmatrix.sync.aligned.m8n8.x4.shared.b16 {%0,%1,%2,%3}, [%4];"
                 : "=r"(r0), "=r"(r1), "=r"(r2), "=r"(r3) : "r"(addr));
}
__device__ __forceinline__ void cp16(unsigned saddr, const void* gptr) {
    asm volatile("cp.async.cg.shared.global [%0], [%1], 16;"
                 :: "r"(saddr), "l"(gptr) : "memory");
}

/* ------------------------- setup ------------------------- */
__global__ void reset_kernel(const int* __restrict__ nbna) {
    int i = blockIdx.x * 256 + threadIdx.x;
    if (i == 0) {
        g_nca = 0; g_ncd = 0; g_nband = 0; g_nhi = 0;
        g_l1s = 0.0; g_l0s = 0ull; g_auxs = 0.0; g_any_dead = 0;
        g_l2s[0] = g_l2s[1] = g_l2s[2] = g_l2s[3] = 0.0;
    }
    if (i < 4096) { g_hist_a[i] = 0; g_hist_d[i] = 0; }
    if (i < B_N) { g_tcnt[i] = 0; g_acnt[i] = 0; }
    if (i < S_N) {
        unsigned char d = (nbna[i] >= 20) ? 1 : 0;
        g_dead[i] = d;
        if (d) g_any_dead = 1;
    }
}

/* dead-feature dense mapping */
__global__ void dm1_kernel() {
    __shared__ int red[1024];
    int i = blockIdx.x * 1024 + threadIdx.x;
    red[threadIdx.x] = g_dead[i] ? 1 : 0;
    __syncthreads();
    for (int s = 512; s > 0; s >>= 1) {
        if (threadIdx.x < s) red[threadIdx.x] += red[threadIdx.x + s];
        __syncthreads();
    }
    if (threadIdx.x == 0) g_dcnt[blockIdx.x] = red[0];
}
__global__ void dm2_kernel() {
    int run = 0;
    for (int b = 0; b < 30; b++) {
        int c = g_dcnt[b];
        g_dcnt[b] = run;
        run += c;
    }
    g_ndead = run;
    g_ndead_pad = (run + 63) & ~63;
}
__global__ void dm3_kernel() {
    __shared__ int sc[1024];
    int i = blockIdx.x * 1024 + threadIdx.x;
    int f = g_dead[i] ? 1 : 0;
    sc[threadIdx.x] = f;
    __syncthreads();
    for (int off = 1; off < 1024; off <<= 1) {
        int v = (threadIdx.x >= off) ? sc[threadIdx.x - off] : 0;
        __syncthreads();
        sc[threadIdx.x] += v;
        __syncthreads();
    }
    if (f) {
        int dense = g_dcnt[blockIdx.x] + sc[threadIdx.x] - 1;
        g_dmap[i] = dense;
        g_dinv[dense] = i;
    }
}

__global__ void zeroA_kernel() {
    size_t tot = (size_t)B_N * (size_t)g_ndead_pad / 4;
    uint2 z = {0u, 0u};
    uint2* p = (uint2*)g_A;
    size_t stride = (size_t)gridDim.x * blockDim.x;
    for (size_t i = blockIdx.x * (size_t)blockDim.x + threadIdx.x; i < tot; i += stride)
        p[i] = z;
}

/* W_dec^T (dead cols) bf16 tiled transpose */
__global__ void wtT_kernel(const float* __restrict__ W_dec) {
    __shared__ float tile[64][65];
    int pad = g_ndead_pad;
    int nd  = g_ndead;
    int j0 = blockIdx.x * 64;
    if (j0 >= pad) return;
    int d0 = blockIdx.y * 64;
    int t = threadIdx.x;
#pragma unroll
    for (int s = 0; s < 16; s++) {
        int idx = t + s * 256;
        int jl = idx >> 6, dl = idx & 63;
        int j = j0 + jl;
        float v = 0.f;
        if (j < nd) v = W_dec[(size_t)g_dinv[j] * D_N + d0 + dl];
        tile[jl][dl] = v;
    }
    __syncthreads();
#pragma unroll
    for (int s = 0; s < 16; s++) {
        int idx = t + s * 256;
        int dl = idx >> 6, jl = idx & 63;
        g_WT[(size_t)(d0 + dl) * pad + j0 + jl] = __float2bfloat16(tile[jl][dl]);
    }
}

/* W_enc transpose: [k][n] f32 -> [n][k] f32 exact + fp16 */
__global__ void whl_kernel(const float* __restrict__ W) {
    __shared__ float tile[64][65];
    int n0 = blockIdx.x * 64;
    int k0 = blockIdx.y * 64;
    int t = threadIdx.x;
#pragma unroll
    for (int s = 0; s < 16; s++) {
        int idx = t + s * 256;
        int kl = idx >> 6, nl = idx & 63;
        tile[kl][nl] = W[(size_t)(k0 + kl) * S_N + n0 + nl];
    }
    __syncthreads();
#pragma unroll
    for (int s = 0; s < 16; s++) {
        int idx = t + s * 256;
        int nl = idx >> 6, kl = idx & 63;
        float v = tile[kl][nl];
        g_WTe[(size_t)(n0 + nl) * D_N + k0 + kl] = v;
        g_Whi[(size_t)(n0 + nl) * D_N + k0 + kl] = __float2half_rn(v);
    }
}

/* scatter COO aux values into dense bf16 A */
__global__ void Ascatter_kernel() {
    int row = blockIdx.x;
    int pad = g_ndead_pad;
    int cnt = min(g_acnt[row], AUXCAP);
    for (int i = threadIdx.x; i < cnt; i += 256) {
        int col = g_acol[(size_t)row * AUXCAP + i];
        float v = g_aval[(size_t)row * AUXCAP + i];
        g_A[(size_t)row * pad + g_dmap[col]] = __float2bfloat16(v);
    }
}

/* xc = x - b_dec  (f32 + fp16) */
__global__ void sub_kernel(const float* __restrict__ x,
                           const float* __restrict__ b_dec) {
    int i = blockIdx.x * 256 + threadIdx.x;
    float4 xv = ((const float4*)x)[i];
    float4 bv = ((const float4*)b_dec)[i & 255];
    float4 o;
    o.x = xv.x - bv.x; o.y = xv.y - bv.y;
    o.z = xv.z - bv.z; o.w = xv.w - bv.w;
    ((float4*)g_xc)[i] = o;
    ((__half2*)g_xhi)[i * 2]     = __floats2half2_rn(o.x, o.y);
    ((__half2*)g_xhi)[i * 2 + 1] = __floats2half2_rn(o.z, o.w);
}

/* ------------- encoder GEMM part 1: fp16 mma.sync, cols [0,NOFF) -------- */
#define EKCH 64
#define ESTR 72
__global__ __launch_bounds__(512) void enc_mma(const float* __restrict__ b_enc,
                                               float* __restrict__ outp)
{
    extern __shared__ __half esm[];
    __half* sA = esm;                    /* [2][128][ESTR] */
    __half* sB = esm + 2 * 128 * ESTR;

    const int tid = threadIdx.x;
    const int wid = tid >> 5, lane = tid & 31;
    const int warp_m = wid & 7;
    const int warp_n = wid >> 3;
    const int bm = blockIdx.x * 128;
    const int bn = blockIdx.y * 128;

    float acc[8][4];
#pragma unroll
    for (int nt = 0; nt < 8; nt++)
#pragma unroll
        for (int q = 0; q < 4; q++) acc[nt][q] = 0.f;

    const int lrow = tid >> 2;
    const int lcol = (tid & 3) * 16;

#define ELOAD(c, b) do {                                                     \
    int kof = (c) * EKCH + lcol;                                             \
    const __half* gA = &g_xhi[(size_t)(bm + lrow) * D_N + kof];              \
    const __half* gB = &g_Whi[(size_t)(bn + lrow) * D_N + kof];              \
    unsigned dA = smem_u32(sA + (b) * 128 * ESTR + lrow * ESTR + lcol);      \
    unsigned dB = smem_u32(sB + (b) * 128 * ESTR + lrow * ESTR + lcol);      \
    cp16(dA, gA); cp16(dA + 16, gA + 8);                                     \
    cp16(dB, gB); cp16(dB + 16, gB + 8);                                     \
    asm volatile("cp.async.commit_group;" ::: "memory");                     \
} while (0)

    ELOAD(0, 0);

    const int lr = (lane & 7) + (lane & 8);
    const int lc = (lane >> 4) << 3;

    for (int c = 0; c < 16; c++) {
        int buf = c & 1;
        if (c < 15) {
            ELOAD(c + 1, buf ^ 1);
            asm volatile("cp.async.wait_group 1;" ::: "memory");
        } else {
            asm volatile("cp.async.wait_group 0;" ::: "memory");
        }
        __syncthreads();
#pragma unroll
        for (int ks = 0; ks < 4; ks++) {
            int k0 = ks * 16;
            unsigned a[4];
            {
                unsigned addr = smem_u32(sA + buf * 128 * ESTR +
                                         (warp_m * 16 + lr) * ESTR + k0 + lc);
                ldm4(a[0], a[1], a[2], a[3], addr);
            }
            unsigned bb[8][2];
#pragma unroll
            for (int p = 0; p < 4; p++) {
                unsigned r0, r1, r2, r3;
                unsigned addr = smem_u32(sB + buf * 128 * ESTR +
                                         (warp_n * 64 + p * 16 + lr) * ESTR + k0 + lc);
                ldm4(r0, r1, r2, r3, addr);
                bb[2 * p][0] = r0; bb[2 * p + 1][0] = r1;
                bb[2 * p][1] = r2; bb[2 * p + 1][1] = r3;
            }
#pragma unroll
            for (int nt = 0; nt < 8; nt++)
                mma_fp16(acc[nt], a, bb[nt]);
        }
        __syncthreads();
    }

    /* epilogue: + b_enc, relu, store f32; also zero out_topk */
    const int crow = lane >> 2, ccol = (lane & 3) * 2;
    const int m1 = bm + warp_m * 16 + crow;
#pragma unroll
    for (int nt = 0; nt < 8; nt++) {
        int n = bn + warp_n * 64 + nt * 8 + ccol;
        float2 be = *(const float2*)&b_enc[n];
        float2 o1, o2;
        o1.x = fmaxf(acc[nt][0] + be.x, 0.f);
        o1.y = fmaxf(acc[nt][1] + be.y, 0.f);
        o2.x = fmaxf(acc[nt][2] + be.x, 0.f);
        o2.y = fmaxf(acc[nt][3] + be.y, 0.f);
        *(float2*)&g_acts[(size_t)m1 * S_N + n] = o1;
        *(float2*)&g_acts[(size_t)(m1 + 8) * S_N + n] = o2;
        outp[(size_t)m1 * S_N + n] = 0.f;
        outp[(size_t)m1 * S_N + n + 1] = 0.f;
        outp[(size_t)(m1 + 8) * S_N + n] = 0.f;
        outp[(size_t)(m1 + 8) * S_N + n + 1] = 0.f;
    }
}

/* ------------- encoder GEMM part 2: f32 FFMA2, cols [NOFF,S_N) ---------- */
__global__ __launch_bounds__(256) void enc_fma(const float* __restrict__ W,
                                               const float* __restrict__ b_enc,
                                               float* __restrict__ outp)
{
    __shared__ float As[2][16][132];
    __shared__ float Bs[2][16][128];
    const int tid = threadIdx.x;
    const int bn = NOFF + blockIdx.x * 128;
    const int bm = blockIdx.y * 128;
    const int tx = tid & 15, ty = tid >> 4;

    unsigned long long acc[8][4];
#pragma unroll
    for (int i = 0; i < 8; i++)
#pragma unroll
        for (int j = 0; j < 4; j++) acc[i][j] = 0ull;

    float4 ra[2], rb[2];
#pragma unroll
    for (int u = 0; u < 2; u++) {
        int id = tid + u * 256;
        ra[u] = *(const float4*)&g_xc[(bm + (id >> 2)) * D_N + (id & 3) * 4];
        rb[u] = *(const float4*)&W[(size_t)(id >> 5) * S_N + bn + (id & 31) * 4];
    }
#pragma unroll
    for (int u = 0; u < 2; u++) {
        int id = tid + u * 256;
        int arow = id >> 2, akq = id & 3;
        As[0][akq * 4 + 0][arow] = ra[u].x;
        As[0][akq * 4 + 1][arow] = ra[u].y;
        As[0][akq * 4 + 2][arow] = ra[u].z;
        As[0][akq * 4 + 3][arow] = ra[u].w;
        *(float4*)&Bs[0][id >> 5][(id & 31) * 4] = rb[u];
    }
    __syncthreads();

    for (int kt = 0; kt < 64; kt++) {
        int s = kt & 1;
        if (kt < 63) {
#pragma unroll
            for (int u = 0; u < 2; u++) {
                int id = tid + u * 256;
                ra[u] = *(const float4*)&g_xc[(bm + (id >> 2)) * D_N + (kt + 1) * 16 + (id & 3) * 4];
                rb[u] = *(const float4*)&W[(size_t)((kt + 1) * 16 + (id >> 5)) * S_N + bn + (id & 31) * 4];
            }
        }
#pragma unroll
        for (int k = 0; k < 16; k++) {
            float4 a0 = *(const float4*)&As[s][k][ty * 4];
            float4 a1 = *(const float4*)&As[s][k][ty * 4 + 64];
            float4 b0 = *(const float4*)&Bs[s][k][tx * 4];
            float4 b1 = *(const float4*)&Bs[s][k][tx * 4 + 64];
            unsigned long long bp0 = pk2(b0.x, b0.y);
            unsigned long long bp1 = pk2(b0.z, b0.w);
            unsigned long long bp2 = pk2(b1.x, b1.y);
            unsigned long long bp3 = pk2(b1.z, b1.w);
            float av[8] = {a0.x, a0.y, a0.z, a0.w, a1.x, a1.y, a1.z, a1.w};
#pragma unroll
            for (int m = 0; m < 8; m++) {
                unsigned long long ad = dup2(av[m]);
                ffma2(acc[m][0], ad, bp0);
                ffma2(acc[m][1], ad, bp1);
                ffma2(acc[m][2], ad, bp2);
                ffma2(acc[m][3], ad, bp3);
            }
        }
        if (kt < 63) {
            int s2 = (kt + 1) & 1;
#pragma unroll
            for (int u = 0; u < 2; u++) {
                int id = tid + u * 256;
                int arow = id >> 2, akq = id & 3;
                As[s2][akq * 4 + 0][arow] = ra[u].x;
                As[s2][akq * 4 + 1][arow] = ra[u].y;
                As[s2][akq * 4 + 2][arow] = ra[u].z;
                As[s2][akq * 4 + 3][arow] = ra[u].w;
                *(float4*)&Bs[s2][id >> 5][(id & 31) * 4] = rb[u];
            }
            __syncthreads();
        }
    }

    float4 be0 = *(const float4*)&b_enc[bn + tx * 4];
    float4 be1 = *(const float4*)&b_enc[bn + tx * 4 + 64];
#pragma unroll
    for (int mh = 0; mh < 2; mh++) {
#pragma unroll
        for (int mi = 0; mi < 4; mi++) {
            int m = mh * 4 + mi;
            size_t grow = (size_t)(bm + mh * 64 + ty * 4 + mi);
#pragma unroll
            for (int nh = 0; nh < 2; nh++) {
                float2 p0 = upk(acc[m][nh * 2 + 0]);
                float2 p1 = upk(acc[m][nh * 2 + 1]);
                float4 be = nh ? be1 : be0;
                float4 o;
                o.x = fmaxf(p0.x + be.x, 0.f);
                o.y = fmaxf(p0.y + be.y, 0.f);
                o.z = fmaxf(p1.x + be.z, 0.f);
                o.w = fmaxf(p1.y + be.w, 0.f);
                size_t base = grow * S_N + bn + nh * 64 + tx * 4;
                *(float4*)&g_acts[base] = o;
                outp[base + 0] = 0.f;
                outp[base + 1] = 0.f;
                outp[base + 2] = 0.f;
                outp[base + 3] = 0.f;
            }
        }
    }
}

/* ------------------------- level-1 histogram ------------------------- */
__global__ void hist1_kernel() {
    __shared__ unsigned ha[4096];
    __shared__ unsigned hd[4096];
    for (int i = threadIdx.x; i < 4096; i += 256) { ha[i] = 0; hd[i] = 0; }
    __syncthreads();
    int t = blockIdx.x * 256 + threadIdx.x;
    const float4* A4 = (const float4*)g_acts;
    for (int r = 0; r < 30; r++) {
        int i4 = t + r * NTHR;
        float4 v = A4[i4];
        int cb = (i4 % SN4) * 4;
        uchar4 dd = *(const uchar4*)&g_dead[cb];
        float vv[4] = {v.x, v.y, v.z, v.w};
        unsigned char dm[4] = {dd.x, dd.y, dd.z, dd.w};
#pragma unroll
        for (int j = 0; j < 4; j++) {
            if (vv[j] > 0.f) {
                unsigned bin = __float_as_uint(vv[j]) >> 20;
                atomicAdd(&ha[bin], 1u);
                if (dm[j]) atomicAdd(&hd[bin], 1u);
            }
        }
    }
    __syncthreads();
    for (int i = threadIdx.x; i < 4096; i += 256) {
        if (ha[i]) atomicAdd(&g_hist_a[i], ha[i]);
        if (hd[i]) atomicAdd(&g_hist_d[i], hd[i]);
    }
}

__global__ void scan1_kernel() {
    if (threadIdx.x == 0) {
        unsigned long long cum = 0;
        for (int b = 4095; b >= 0; b--) {
            cum += g_hist_a[b];
            if (cum >= (unsigned long long)KTOP) {
                g_b1a = b; g_r1a = KTOP - (unsigned)(cum - g_hist_a[b]); break;
            }
        }
        cum = 0;
        for (int b = 4095; b >= 0; b--) {
            cum += g_hist_d[b];
            if (cum >= (unsigned long long)KAUX) {
                g_b1d = b; g_r1d = KAUX - (unsigned)(cum - g_hist_d[b]); break;
            }
        }
    }
    __syncthreads();
    for (int i = threadIdx.x; i < 4096; i += 256) { g_hist_a[i] = 0; g_hist_d[i] = 0; }
}

/* ------------------------- candidate compaction ------------------------- */
__device__ __forceinline__ void wappend(unsigned* buf, int* ctr, unsigned cap,
                                        bool pred, unsigned val) {
    unsigned m = __ballot_sync(0xffffffffu, pred);
    if (!m) return;
    int lane = threadIdx.x & 31;
    int leader = __ffs(m) - 1;
    int base = 0;
    if (lane == leader) base = atomicAdd(ctr, __popc(m));
    base = __shfl_sync(0xffffffffu, base, leader);
    if (pred) {
        int pos = base + __popc(m & ((1u << lane) - 1u));
        if ((unsigned)pos < cap) buf[pos] = val;
    }
}

__global__ void compact_kernel() {
    int t = blockIdx.x * 256 + threadIdx.x;
    const unsigned b1a = (unsigned)g_b1a, b1d = (unsigned)g_b1d;
    const float4* A4 = (const float4*)g_acts;
    for (int r = 0; r < 30; r++) {
        int i4 = t + r * NTHR;
        float4 v = A4[i4];
        int cb = (i4 % SN4) * 4;
        uchar4 dd = *(const uchar4*)&g_dead[cb];
        float vv[4] = {v.x, v.y, v.z, v.w};
        unsigned char dm[4] = {dd.x, dd.y, dd.z, dd.w};
#pragma unroll
        for (int j = 0; j < 4; j++) {
            unsigned u = __float_as_uint(vv[j]);
            bool pos = vv[j] > 0.f;
            wappend(g_cand_a, &g_nca, CANDCAP, pos && ((u >> 20) == b1a), u);
            wappend(g_cand_d, &g_ncd, CANDCAP, pos && dm[j] && ((u >> 20) == b1d), u);
        }
    }
}

/* ------------------------- level-2 refine + thresholds ------------------ */
__global__ void hist2_kernel() {
    __shared__ unsigned ha[4096];
    __shared__ unsigned hd[4096];
    for (int i = threadIdx.x; i < 4096; i += 256) { ha[i] = 0; hd[i] = 0; }
    __syncthreads();
    int stride = gridDim.x * 256;
    int t0 = blockIdx.x * 256 + threadIdx.x;
    int na = min(g_nca, (int)CANDCAP), nd = min(g_ncd, (int)CANDCAP);
    for (int i = t0; i < na; i += stride) atomicAdd(&ha[(g_cand_a[i] >> 8) & 0xFFF], 1u);
    for (int i = t0; i < nd; i += stride) atomicAdd(&hd[(g_cand_d[i] >> 8) & 0xFFF], 1u);
    __syncthreads();
    for (int i = threadIdx.x; i < 4096; i += 256) {
        if (ha[i]) atomicAdd(&g_hist_a[i], ha[i]);
        if (hd[i]) atomicAdd(&g_hist_d[i], hd[i]);
    }
}

__global__ void scan2_kernel() {
    if (threadIdx.x == 0) {
        unsigned long long cum = 0; unsigned K = g_r1a;
        for (int b = 4095; b >= 0; b--) {
            cum += g_hist_a[b];
            if (cum >= (unsigned long long)K) { g_b2a = b; break; }
        }
        cum = 0; K = g_r1d;
        for (int b = 4095; b >= 0; b--) {
            cum += g_hist_d[b];
            if (cum >= (unsigned long long)K) { g_b2d = b; break; }
        }
        g_tba = ((unsigned)g_b1a << 20) | ((unsigned)g_b2a << 8);
        g_tbd = ((unsigned)g_b1d << 20) | ((unsigned)g_b2d << 8);
        float t = __uint_as_float(g_tba);
        g_hib = __float_as_uint(t * (1.0f + 3.2e-3f));
        g_lob = __float_as_uint(t * (1.0f - 3.0e-3f));
    }
}

/* ------------------------- scatter (sparse commits) --------------------- */
__global__ void scatter_kernel(float* __restrict__ outp) {
    __shared__ float redf[256];
    __shared__ int redi[256];
    const unsigned hib = g_hib;
    const unsigned lob = g_lob;
    const float td = __uint_as_float(g_tbd);
    int t = blockIdx.x * 256 + threadIdx.x;
    float l1loc = 0.f;
    int l0loc = 0;
#pragma unroll 4
    for (int r = 0; r < 120; r++) {
        int i = t + r * NTHR;
        float v = g_acts[i];
        int row = i / S_N;
        int col = i - row * S_N;
        unsigned u = __float_as_uint(v);
        bool pos = v > 0.f;
        bool keep = pos && (u > hib);
        if (keep) {
            outp[i] = v;
            l1loc += v; l0loc++;
            int p = atomicAdd(&g_tcnt[row], 1);
            if (p < TOPCAP) {
                g_tcol[row * TOPCAP + p] = (unsigned short)col;
                g_tval[row * TOPCAP + p] = v;
            }
        }
        wappend((unsigned*)g_bidx, &g_nband, BANDCAP,
                pos && !keep && (u > lob), (unsigned)i);
        if (g_dead[col]) {
            float d = v - td;
            if (d > 0.f) {
                int p = atomicAdd(&g_acnt[row], 1);
                if (p < AUXCAP) {
                    g_acol[(size_t)row * AUXCAP + p] = (unsigned short)col;
                    g_aval[(size_t)row * AUXCAP + p] = d;
                }
            }
        }
    }
    redf[threadIdx.x] = l1loc;
    redi[threadIdx.x] = l0loc;
    __syncthreads();
    for (int s = 128; s > 0; s >>= 1) {
        if (threadIdx.x < s) {
            redf[threadIdx.x] += redf[threadIdx.x + s];
            redi[threadIdx.x] += redi[threadIdx.x + s];
        }
        __syncthreads();
    }
    if (threadIdx.x == 0) {
        atomicAdd(&g_l1s, (double)redf[0]);
        atomicAdd(&g_l0s, (unsigned long long)redi[0]);
        atomicAdd(&g_nhi, redi[0]);
    }
}

/* ------------------------- exact dot (double-f32, coalesced WTe) -------- */
__device__ __forceinline__ void exact_dot(int row, int col, int lane,
                                          float& sh_out, float& sl_out) {
    const float* xr = &g_xc[row * D_N];
    const float* wr = &g_WTe[(size_t)col * D_N];
    float sh = 0.f, sl = 0.f;
#pragma unroll 4
    for (int j = 0; j < 32; j++) {
        int k = lane + j * 32;
        float a = xr[k], b = wr[k];
        float ph = fmul_rn(a, b);
        float pl = ffma_rn(a, b, -ph);
        float s  = fadd_rn(sh, ph);
        float bb = fsub_rn(s, sh);
        float e1 = fsub_rn(sh, fsub_rn(s, bb));
        float e2 = fsub_rn(ph, bb);
        sh = s;
        sl = fadd_rn(sl, fadd_rn(fadd_rn(e1, e2), pl));
    }
    for (int off = 16; off; off >>= 1) {
        float oh = __shfl_down_sync(0xffffffffu, sh, off);
        float ol = __shfl_down_sync(0xffffffffu, sl, off);
        float s  = fadd_rn(sh, oh);
        float bb = fsub_rn(s, sh);
        float e1 = fsub_rn(sh, fsub_rn(s, bb));
        float e2 = fsub_rn(oh, bb);
        sh = s;
        sl = fadd_rn(sl, fadd_rn(fadd_rn(e1, e2), ol));
    }
    sh_out = sh; sl_out = sl;
}

/* exact band dots */
__global__ void band_dot_kernel(const float* __restrict__ b_enc) {
    int w = (blockIdx.x * 256 + threadIdx.x) >> 5;
    int lane = threadIdx.x & 31;
    int nb = min(g_nband, (int)BANDCAP);
    if (w >= nb) return;
    int idx = g_bidx[w];
    int row = idx / S_N, col = idx - row * S_N;
    float sh, sl;
    exact_dot(row, col, lane, sh, sl);
    if (lane == 0) {
        double val = (double)sh + (double)sl + (double)b_enc[col];
        float hh = (float)val;
        g_bhi[w] = hh;
        g_blo[w] = (float)(val - (double)hh);
    }
}

/* ------------------------- band ranking + commit (16K bitonic) -------- */
__global__ __launch_bounds__(1024) void band_rank_kernel(float* __restrict__ outp) {
    extern __shared__ char bsm[];
    double* sval = (double*)bsm;
    int*    sidx = (int*)(bsm + (size_t)BANDCAP * 8);
    __shared__ double rsm[32];
    int tid = threadIdx.x;
    int nb = min(g_nband, (int)BANDCAP);
    for (int i = tid; i < BANDCAP; i += 1024) {
        if (i < nb) {
            sval[i] = (double)g_bhi[i] + (double)g_blo[i];
            sidx[i] = g_bidx[i];
        } else {
            sval[i] = -1e300;
            sidx[i] = 0x7fffffff;
        }
    }
    __syncthreads();
    for (int size = 2; size <= BANDCAP; size <<= 1) {
        for (int stride = size >> 1; stride; stride >>= 1) {
            for (int i = tid; i < BANDCAP / 2; i += 1024) {
                int pos = 2 * i - (i & (stride - 1));
                int a = pos, b = pos + stride;
                bool dirDesc = ((pos & size) == 0);
                bool agtb = (sval[a] != sval[b]) ? (sval[a] > sval[b])
                                                 : (sidx[a] < sidx[b]);
                if (dirDesc ? !agtb : agtb) {
                    double tv = sval[a]; sval[a] = sval[b]; sval[b] = tv;
                    int ti = sidx[a]; sidx[a] = sidx[b]; sidx[b] = ti;
                }
            }
            __syncthreads();
        }
    }
    int needK = (int)KTOP - g_nhi;
    if (needK < 0) needK = 0;
    if (needK > nb) needK = nb;
    double l1loc = 0.0;
    for (int i = tid; i < needK; i += 1024) {
        int idx = sidx[i];
        float fv = (float)sval[i];
        outp[idx] = fv;
        int row = idx / S_N, col = idx - row * S_N;
        int p = atomicAdd(&g_tcnt[row], 1);
        if (p < TOPCAP) {
            g_tcol[row * TOPCAP + p] = (unsigned short)col;
            g_tval[row * TOPCAP + p] = fv;
        }
        l1loc += (double)fv;
    }
    for (int off = 16; off; off >>= 1)
        l1loc += __shfl_down_sync(0xffffffffu, l1loc, off);
    if ((tid & 31) == 0) rsm[tid >> 5] = l1loc;
    __syncthreads();
    if (tid == 0) {
        double s = 0.0;
        for (int q = 0; q < 32; q++) s += rsm[q];
        atomicAdd(&g_l1s, s);
        atomicAdd(&g_l0s, (unsigned long long)needK);
    }
}

/* ------------------------- sparse Matryoshka decode ------------------------- */
__global__ void decode_kernel(const float* __restrict__ x,
                              const float* __restrict__ b_dec,
                              const float* __restrict__ W_dec,
                              float* __restrict__ out_recon)
{
    __shared__ unsigned short scol[TOPCAP];
    __shared__ float sval[TOPCAP];
    __shared__ float red[256];
    int row = blockIdx.x, tid = threadIdx.x;
    int cnt = min(g_tcnt[row], TOPCAP);
    for (int i = tid; i < cnt; i += 256) {
        scol[i] = g_tcol[row * TOPCAP + i];
        sval[i] = g_tval[row * TOPCAP + i];
    }
    __syncthreads();
    int d = tid * 4;
    float4 acc = *(const float4*)&b_dec[d];
    float4 xv = *(const float4*)&x[row * D_N + d];
    const int bounds[5] = {0, 2048, 6144, 14336, 30720};
#pragma unroll
    for (int g = 0; g < 4; g++) {
        int lo = bounds[g], hi = bounds[g + 1];
        for (int e = 0; e < cnt; e++) {
            int c = scol[e];
            if (c >= lo && c < hi) {
                float vv = sval[e];
                float4 w = *(const float4*)&W_dec[(size_t)c * D_N + d];
                acc.x += vv * w.x; acc.y += vv * w.y;
                acc.z += vv * w.z; acc.w += vv * w.w;
            }
        }
        float dx = acc.x - xv.x, dy = acc.y - xv.y;
        float dz = acc.z - xv.z, dw = acc.w - xv.w;
        red[tid] = dx * dx + dy * dy + dz * dz + dw * dw;
        __syncthreads();
        for (int s = 128; s > 0; s >>= 1) {
            if (tid < s) red[tid] += red[tid + s];
            __syncthreads();
        }
        if (tid == 0) atomicAdd(&g_l2s[g], (double)red[0]);
        __syncthreads();
    }
    float* ro = out_recon + (size_t)row * D_N + d;
    ro[0] = acc.x; ro[1] = acc.y; ro[2] = acc.z; ro[3] = acc.w;
    *(float4*)&g_recon[row * D_N + d] = acc;
}

/* ------------------------- aux dense GEMM (smem + ldmatrix + mma.sync) ------- */
#define KCH 32
#define SSTR 40
__global__ __launch_bounds__(256) void aux_gemm(const float* __restrict__ x)
{
    __shared__ __align__(16) __nv_bfloat16 sA[2][128][SSTR];
    __shared__ __align__(16) __nv_bfloat16 sB[2][128][SSTR];
    __shared__ float wsum[8];

    if (g_ndead == 0) return;
    const int pad = g_ndead_pad;
    const int nchunks = pad / KCH;
    const int tid = threadIdx.x;
    const int wid = tid >> 5;
    const int lane = tid & 31;
    const int warp_m = wid & 3;
    const int warp_n = wid >> 2;
    const int bm = blockIdx.x * 128;
    const int bn = blockIdx.y * 128;
    const int m0 = bm + warp_m * 32;
    const int n0l = warp_n * 64;

    float acc[2][8][4];
#pragma unroll
    for (int mt = 0; mt < 2; mt++)
#pragma unroll
        for (int nt = 0; nt < 8; nt++)
#pragma unroll
            for (int q = 0; q < 4; q++) acc[mt][nt][q] = 0.f;

    const int lrow = tid >> 1;
    const int lseg = tid & 1;

#define LOAD_CHUNK(c, b)                                                        \
    do {                                                                        \
        int kof = (c) * KCH;                                                    \
        cp16(smem_u32(&sA[b][lrow][(lseg) * 8]),                                \
             &g_A[(size_t)(bm + lrow) * pad + kof + (lseg) * 8]);               \
        cp16(smem_u32(&sA[b][lrow][(lseg + 2) * 8]),                            \
             &g_A[(size_t)(bm + lrow) * pad + kof + (lseg + 2) * 8]);           \
        cp16(smem_u32(&sB[b][lrow][(lseg) * 8]),                                \
             &g_WT[(size_t)(bn + lrow) * pad + kof + (lseg) * 8]);              \
        cp16(smem_u32(&sB[b][lrow][(lseg + 2) * 8]),                            \
             &g_WT[(size_t)(bn + lrow) * pad + kof + (lseg + 2) * 8]);          \
        asm volatile("cp.async.commit_group;" ::: "memory");                    \
    } while (0)

    LOAD_CHUNK(0, 0);

    const int lr = (lane & 7) + (lane & 8);
    const int lc = (lane >> 4) << 3;

    for (int c = 0; c < nchunks; c++) {
        int buf = c & 1;
        if (c + 1 < nchunks) {
            LOAD_CHUNK(c + 1, (c + 1) & 1);
            asm volatile("cp.async.wait_group 1;" ::: "memory");
        } else {
            asm volatile("cp.async.wait_group 0;" ::: "memory");
        }
        __syncthreads();

#pragma unroll
        for (int ks = 0; ks < KCH / 16; ks++) {
            int k0 = ks * 16;
            unsigned a[2][4];
#pragma unroll
            for (int mt = 0; mt < 2; mt++) {
                unsigned addr = smem_u32(&sA[buf][warp_m * 32 + mt * 16 + lr][k0 + lc]);
                ldm4(a[mt][0], a[mt][1], a[mt][2], a[mt][3], addr);
            }
            unsigned bb[8][2];
#pragma unroll
            for (int p = 0; p < 4; p++) {
                unsigned r0, r1, r2, r3;
                unsigned addr = smem_u32(&sB[buf][n0l + p * 16 + lr][k0 + lc]);
                ldm4(r0, r1, r2, r3, addr);
                bb[2 * p][0] = r0; bb[2 * p + 1][0] = r1;
                bb[2 * p][1] = r2; bb[2 * p + 1][1] = r3;
            }
#pragma unroll
            for (int mt = 0; mt < 2; mt++)
#pragma unroll
                for (int nt = 0; nt < 8; nt++)
                    mma_bf16(acc[mt][nt], a[mt], bb[nt]);
        }
        __syncthreads();
    }

    const int crow = lane >> 2;
    const int ccol = (lane & 3) * 2;
    const int n0 = bn + n0l;
    float sum = 0.f;
#pragma unroll
    for (int mt = 0; mt < 2; mt++) {
#pragma unroll
        for (int nt = 0; nt < 8; nt++) {
            int m1 = m0 + mt * 16 + crow;
            int m2 = m1 + 8;
            int dd = n0 + nt * 8 + ccol;
            float2 xv1 = *(const float2*)&x[(size_t)m1 * D_N + dd];
            float2 rv1 = *(const float2*)&g_recon[(size_t)m1 * D_N + dd];
            float2 xv2 = *(const float2*)&x[(size_t)m2 * D_N + dd];
            float2 rv2 = *(const float2*)&g_recon[(size_t)m2 * D_N + dd];
            float d0 = acc[mt][nt][0] - (xv1.x - rv1.x);
            float d1 = acc[mt][nt][1] - (xv1.y - rv1.y);
            float d2 = acc[mt][nt][2] - (xv2.x - rv2.x);
            float d3 = acc[mt][nt][3] - (xv2.y - rv2.y);
            sum += d0 * d0 + d1 * d1 + d2 * d2 + d3 * d3;
        }
    }
    for (int off = 16; off; off >>= 1)
        sum += __shfl_down_sync(0xffffffffu, sum, off);
    if (lane == 0) wsum[wid] = sum;
    __syncthreads();
    if (tid == 0) {
        float s = 0.f;
        for (int w = 0; w < 8; w++) s += wsum[w];
        atomicAdd(&g_auxs, (double)s);
    }
}

/* ------------------------- finalize ------------------------- */
__global__ void fin_kernel(float* __restrict__ out) {
    double inv = 1.0 / ((double)B_N * (double)D_N);
    double l2m = (g_l2s[0] + g_l2s[1] + g_l2s[2] + g_l2s[3]) * 0.25 * inv;
    double l1 = 1e-3 * g_l1s / (double)B_N;
    double l0 = (double)g_l0s / (double)B_N;
    double aux = g_any_dead ? (1e-2 * g_auxs * inv) : 0.0;
    out[0] = (float)(l2m + l1 + aux);
    out[1] = (float)l2m;
    out[2] = (float)l1;
    out[3] = (float)aux;
    out[4] = (float)l0;
}

/* ------------------------- launch ------------------------- */
extern "C" void kernel_launch(void* const* d_in, const int* in_sizes, int n_in,
                              void* d_out, int out_size) {
    const float* x     = (const float*)d_in[0];
    const float* b_dec = (const float*)d_in[1];
    const float* b_enc = (const float*)d_in[2];
    const float* W_enc = (const float*)d_in[3];
    const float* W_dec = (const float*)d_in[4];
    const int*   nbna  = (const int*)d_in[5];
    float* out = (float*)d_out;
    float* out_topk  = out + 5;
    float* out_recon = out + 5 + (size_t)B_N * S_N;

    static int init_done = 0;
    static cudaStream_t s1, s2;
    static cudaEvent_t eA, eSub, eF, eS, eAs;
    if (!init_done) {
        cudaFuncSetAttribute(enc_mma, cudaFuncAttributeMaxDynamicSharedMemorySize,
                             4 * 128 * ESTR * 2);
        cudaFuncSetAttribute(band_rank_kernel,
                             cudaFuncAttributeMaxDynamicSharedMemorySize,
                             BANDCAP * 12);
        cudaStreamCreateWithFlags(&s1, cudaStreamNonBlocking);
        cudaStreamCreateWithFlags(&s2, cudaStreamNonBlocking);
        cudaEventCreateWithFlags(&eA,   cudaEventDisableTiming);
        cudaEventCreateWithFlags(&eSub, cudaEventDisableTiming);
        cudaEventCreateWithFlags(&eF,   cudaEventDisableTiming);
        cudaEventCreateWithFlags(&eS,   cudaEventDisableTiming);
        cudaEventCreateWithFlags(&eAs,  cudaEventDisableTiming);
        init_done = 1;
    }

    /* main stream: reset, then fork prep chain onto s1 */
    reset_kernel<<<(S_N + 255) / 256, 256>>>(nbna);
    cudaEventRecord(eA, 0);
    cudaStreamWaitEvent(s1, eA, 0);
    dm1_kernel<<<30, 1024, 0, s1>>>();
    dm2_kernel<<<1, 1, 0, s1>>>();
    dm3_kernel<<<30, 1024, 0, s1>>>();
    zeroA_kernel<<<2048, 256, 0, s1>>>();
    wtT_kernel<<<dim3(S_N / 64, D_N / 64), 256, 0, s1>>>(W_dec);

    /* main: sub, then fork fma-encoder onto s2 */
    sub_kernel<<<B_N * D_N / 4 / 256, 256>>>(x, b_dec);
    cudaEventRecord(eSub, 0);
    cudaStreamWaitEvent(s2, eSub, 0);
    enc_fma<<<dim3((S_N - NOFF) / 128, B_N / 128), 256, 0, s2>>>(W_enc, b_enc, out_topk);
    cudaEventRecord(eF, s2);

    whl_kernel<<<dim3(S_N / 64, D_N / 64), 256>>>(W_enc);
    enc_mma<<<dim3(B_N / 128, NOFF / 128), 512, 4 * 128 * ESTR * 2>>>(b_enc, out_topk);
    cudaStreamWaitEvent(0, eF, 0);

    hist1_kernel<<<2048, 256>>>();
    scan1_kernel<<<1, 256>>>();
    compact_kernel<<<2048, 256>>>();
    hist2_kernel<<<512, 256>>>();
    scan2_kernel<<<1, 256>>>();
    scatter_kernel<<<2048, 256>>>(out_topk);
    cudaEventRecord(eS, 0);

    /* s1: Ascatter (needs dm3 + scatter), overlapped with band/decode */
    cudaStreamWaitEvent(s1, eS, 0);
    Ascatter_kernel<<<B_N, 256, 0, s1>>>();
    cudaEventRecord(eAs, s1);

    band_dot_kernel<<<BANDCAP / 8, 256>>>(b_enc);
    band_rank_kernel<<<1, 1024, BANDCAP * 12>>>(out_topk);
    decode_kernel<<<B_N, 256>>>(x, b_dec, W_dec, out_recon);
    cudaStreamWaitEvent(0, eAs, 0);
    aux_gemm<<<dim3(B_N / 128, D_N / 128), 256>>>(x);
    fin_kernel<<<1, 1>>>(out);
}

// round 14
// speedup vs baseline: 1.1021x; 1.1021x over previous
#include <cuda_runtime.h>
#include <cuda_bf16.h>
#include <cuda_fp16.h>
#include <cstdint>

#define B_N   2048
#define D_N   1024
#define S_N   30720
#define SN4   7680
#define NTHR  524288
#define KTOP  131072u
#define KAUX  2097152u
#define TOPCAP 160
#define AUXCAP 2048
#define BANDCAP 16384
#define CANDCAP (4u<<20)

/* ------------------------- scratch ------------------------- */
__device__ float g_acts[(size_t)B_N * S_N];
__device__ float g_xc[B_N * D_N];
__device__ float g_recon[B_N * D_N];
__device__ unsigned g_hist_a[4096];
__device__ unsigned g_hist_d[4096];
__device__ unsigned char g_dead[S_N];
__device__ int g_any_dead;
__device__ unsigned g_cand_a[CANDCAP];
__device__ unsigned g_cand_d[CANDCAP];
__device__ int g_nca, g_ncd;
__device__ int g_b1a, g_b1d, g_b2a, g_b2d;
__device__ unsigned g_r1a, g_r1d;
__device__ unsigned g_tba, g_tbd;
__device__ unsigned g_hib, g_lob;
__device__ int g_bidx[BANDCAP];
__device__ float g_bhi[BANDCAP], g_blo[BANDCAP];
__device__ int g_nband, g_nhi;
__device__ unsigned short g_tcol[B_N * TOPCAP];
__device__ float          g_tval[B_N * TOPCAP];
__device__ int            g_tcnt[B_N];
__device__ unsigned short g_acol[(size_t)B_N * AUXCAP];
__device__ float          g_aval[(size_t)B_N * AUXCAP];
__device__ int            g_acnt[B_N];
__device__ double g_l2s[4];
__device__ double g_l1s;
__device__ unsigned long long g_l0s;
__device__ double g_auxs;

/* encoder fp16 GEMM scratch */
__device__ __half g_xhi[B_N * D_N];
__device__ __half g_Whi[(size_t)S_N * D_N];          /* W_enc^T fp16 [n][k] */
__device__ float  g_WTe[(size_t)S_N * D_N];          /* W_enc^T exact f32 [n][k] */

/* dense aux GEMM scratch */
__device__ __nv_bfloat16 g_A[(size_t)B_N * S_N];
__device__ __nv_bfloat16 g_WT[(size_t)D_N * S_N];
__device__ int g_dmap[S_N];
__device__ int g_dinv[S_N];
__device__ int g_dcnt[32];
__device__ int g_ndead, g_ndead_pad;

/* ------------------------- exact f32 helpers ------------------------- */
__device__ __forceinline__ float fadd_rn(float a, float b) {
    float r; asm("add.rn.f32 %0, %1, %2;" : "=f"(r) : "f"(a), "f"(b)); return r;
}
__device__ __forceinline__ float fsub_rn(float a, float b) {
    float r; asm("sub.rn.f32 %0, %1, %2;" : "=f"(r) : "f"(a), "f"(b)); return r;
}
__device__ __forceinline__ float fmul_rn(float a, float b) {
    float r; asm("mul.rn.f32 %0, %1, %2;" : "=f"(r) : "f"(a), "f"(b)); return r;
}
__device__ __forceinline__ float ffma_rn(float a, float b, float c) {
    float r; asm("fma.rn.f32 %0, %1, %2, %3;" : "=f"(r) : "f"(a), "f"(b), "f"(c)); return r;
}

/* mma.sync bf16 / fp16 (baseline PTX, plain sm_103) */
__device__ __forceinline__ void mma_bf16(float* c, const unsigned* a, const unsigned* b) {
    asm volatile(
        "mma.sync.aligned.m16n8k16.row.col.f32.bf16.bf16.f32 "
        "{%0,%1,%2,%3}, {%4,%5,%6,%7}, {%8,%9}, {%0,%1,%2,%3};"
        : "+f"(c[0]), "+f"(c[1]), "+f"(c[2]), "+f"(c[3])
        : "r"(a[0]), "r"(a[1]), "r"(a[2]), "r"(a[3]), "r"(b[0]), "r"(b[1]));
}
__device__ __forceinline__ void mma_fp16(float* c, const unsigned* a, const unsigned* b) {
    asm volatile(
        "mma.sync.aligned.m16n8k16.row.col.f32.f16.f16.f32 "
        "{%0,%1,%2,%3}, {%4,%5,%6,%7}, {%8,%9}, {%0,%1,%2,%3};"
        : "+f"(c[0]), "+f"(c[1]), "+f"(c[2]), "+f"(c[3])
        : "r"(a[0]), "r"(a[1]), "r"(a[2]), "r"(a[3]), "r"(b[0]), "r"(b[1]));
}
__device__ __forceinline__ uint32_t smem_u32(const void* p) {
    uint32_t a;
    asm("{ .reg .u64 t; cvta.to.shared.u64 t, %1; cvt.u32.u64 %0, t; }"
        : "=r"(a) : "l"(p));
    return a;
}
__device__ __forceinline__ void ldm4(unsigned &r0, unsigned &r1,
                                     unsigned &r2, unsigned &r3, unsigned addr) {
    asm volatile("ldmatrix.sync.aligned.m8n8.x4.shared.b16 {%0,%1,%2,%3}, [%4];"
                 : "=r"(r0), "=r"(r1), "=r"(r2), "=r"(r3) : "r"(addr));
}
__device__ __forceinline__ void cp16(unsigned saddr, const void* gptr) {
    asm volatile("cp.async.cg.shared.global [%0], [%1], 16;"
                 :: "r"(saddr), "l"(gptr) : "memory");
}

/* ------------------------- setup ------------------------- */
__global__ void reset_kernel(const int* __restrict__ nbna) {
    int i = blockIdx.x * 256 + threadIdx.x;
    if (i == 0) {
        g_nca = 0; g_ncd = 0; g_nband = 0; g_nhi = 0;
        g_l1s = 0.0; g_l0s = 0ull; g_auxs = 0.0; g_any_dead = 0;
        g_l2s[0] = g_l2s[1] = g_l2s[2] = g_l2s[3] = 0.0;
    }
    if (i < 4096) { g_hist_a[i] = 0; g_hist_d[i] = 0; }
    if (i < B_N) { g_tcnt[i] = 0; g_acnt[i] = 0; }
    if (i < S_N) {
        unsigned char d = (nbna[i] >= 20) ? 1 : 0;
        g_dead[i] = d;
        if (d) g_any_dead = 1;
    }
}

/* dead-feature dense mapping */
__global__ void dm1_kernel() {
    __shared__ int red[1024];
    int i = blockIdx.x * 1024 + threadIdx.x;
    red[threadIdx.x] = g_dead[i] ? 1 : 0;
    __syncthreads();
    for (int s = 512; s > 0; s >>= 1) {
        if (threadIdx.x < s) red[threadIdx.x] += red[threadIdx.x + s];
        __syncthreads();
    }
    if (threadIdx.x == 0) g_dcnt[blockIdx.x] = red[0];
}
__global__ void dm2_kernel() {
    int run = 0;
    for (int b = 0; b < 30; b++) {
        int c = g_dcnt[b];
        g_dcnt[b] = run;
        run += c;
    }
    g_ndead = run;
    g_ndead_pad = (run + 63) & ~63;
}
__global__ void dm3_kernel() {
    __shared__ int sc[1024];
    int i = blockIdx.x * 1024 + threadIdx.x;
    int f = g_dead[i] ? 1 : 0;
    sc[threadIdx.x] = f;
    __syncthreads();
    for (int off = 1; off < 1024; off <<= 1) {
        int v = (threadIdx.x >= off) ? sc[threadIdx.x - off] : 0;
        __syncthreads();
        sc[threadIdx.x] += v;
        __syncthreads();
    }
    if (f) {
        int dense = g_dcnt[blockIdx.x] + sc[threadIdx.x] - 1;
        g_dmap[i] = dense;
        g_dinv[dense] = i;
    }
}

__global__ void zeroA_kernel() {
    size_t tot = (size_t)B_N * (size_t)g_ndead_pad / 4;
    uint2 z = {0u, 0u};
    uint2* p = (uint2*)g_A;
    size_t stride = (size_t)gridDim.x * blockDim.x;
    for (size_t i = blockIdx.x * (size_t)blockDim.x + threadIdx.x; i < tot; i += stride)
        p[i] = z;
}

/* W_dec^T (dead cols) bf16 tiled transpose */
__global__ void wtT_kernel(const float* __restrict__ W_dec) {
    __shared__ float tile[64][65];
    int pad = g_ndead_pad;
    int nd  = g_ndead;
    int j0 = blockIdx.x * 64;
    if (j0 >= pad) return;
    int d0 = blockIdx.y * 64;
    int t = threadIdx.x;
#pragma unroll
    for (int s = 0; s < 16; s++) {
        int idx = t + s * 256;
        int jl = idx >> 6, dl = idx & 63;
        int j = j0 + jl;
        float v = 0.f;
        if (j < nd) v = W_dec[(size_t)g_dinv[j] * D_N + d0 + dl];
        tile[jl][dl] = v;
    }
    __syncthreads();
#pragma unroll
    for (int s = 0; s < 16; s++) {
        int idx = t + s * 256;
        int dl = idx >> 6, jl = idx & 63;
        g_WT[(size_t)(d0 + dl) * pad + j0 + jl] = __float2bfloat16(tile[jl][dl]);
    }
}

/* W_enc transpose: [k][n] f32 -> [n][k] f32 exact + fp16 */
__global__ void whl_kernel(const float* __restrict__ W) {
    __shared__ float tile[64][65];
    int n0 = blockIdx.x * 64;
    int k0 = blockIdx.y * 64;
    int t = threadIdx.x;
#pragma unroll
    for (int s = 0; s < 16; s++) {
        int idx = t + s * 256;
        int kl = idx >> 6, nl = idx & 63;
        tile[kl][nl] = W[(size_t)(k0 + kl) * S_N + n0 + nl];
    }
    __syncthreads();
#pragma unroll
    for (int s = 0; s < 16; s++) {
        int idx = t + s * 256;
        int nl = idx >> 6, kl = idx & 63;
        float v = tile[kl][nl];
        g_WTe[(size_t)(n0 + nl) * D_N + k0 + kl] = v;
        g_Whi[(size_t)(n0 + nl) * D_N + k0 + kl] = __float2half_rn(v);
    }
}

/* scatter COO aux values into dense bf16 A */
__global__ void Ascatter_kernel() {
    int row = blockIdx.x;
    int pad = g_ndead_pad;
    int cnt = min(g_acnt[row], AUXCAP);
    for (int i = threadIdx.x; i < cnt; i += 256) {
        int col = g_acol[(size_t)row * AUXCAP + i];
        float v = g_aval[(size_t)row * AUXCAP + i];
        g_A[(size_t)row * pad + g_dmap[col]] = __float2bfloat16(v);
    }
}

/* xc = x - b_dec  (f32 + fp16) */
__global__ void sub_kernel(const float* __restrict__ x,
                           const float* __restrict__ b_dec) {
    int i = blockIdx.x * 256 + threadIdx.x;
    float4 xv = ((const float4*)x)[i];
    float4 bv = ((const float4*)b_dec)[i & 255];
    float4 o;
    o.x = xv.x - bv.x; o.y = xv.y - bv.y;
    o.z = xv.z - bv.z; o.w = xv.w - bv.w;
    ((float4*)g_xc)[i] = o;
    ((__half2*)g_xhi)[i * 2]     = __floats2half2_rn(o.x, o.y);
    ((__half2*)g_xhi)[i * 2 + 1] = __floats2half2_rn(o.z, o.w);
}

/* ------------- encoder GEMM (fp16 mma.sync), zeroes out_topk ---------- */
#define EKCH 64
#define ESTR 72
__global__ __launch_bounds__(512) void enc_mma(const float* __restrict__ b_enc,
                                               float* __restrict__ outp)
{
    extern __shared__ __half esm[];
    __half* sA = esm;                    /* [2][128][ESTR] */
    __half* sB = esm + 2 * 128 * ESTR;

    const int tid = threadIdx.x;
    const int wid = tid >> 5, lane = tid & 31;
    const int warp_m = wid & 7;
    const int warp_n = wid >> 3;
    const int bm = blockIdx.x * 128;
    const int bn = blockIdx.y * 128;

    float acc[8][4];
#pragma unroll
    for (int nt = 0; nt < 8; nt++)
#pragma unroll
        for (int q = 0; q < 4; q++) acc[nt][q] = 0.f;

    const int lrow = tid >> 2;
    const int lcol = (tid & 3) * 16;

#define ELOAD(c, b) do {                                                     \
    int kof = (c) * EKCH + lcol;                                             \
    const __half* gA = &g_xhi[(size_t)(bm + lrow) * D_N + kof];              \
    const __half* gB = &g_Whi[(size_t)(bn + lrow) * D_N + kof];              \
    unsigned dA = smem_u32(sA + (b) * 128 * ESTR + lrow * ESTR + lcol);      \
    unsigned dB = smem_u32(sB + (b) * 128 * ESTR + lrow * ESTR + lcol);      \
    cp16(dA, gA); cp16(dA + 16, gA + 8);                                     \
    cp16(dB, gB); cp16(dB + 16, gB + 8);                                     \
    asm volatile("cp.async.commit_group;" ::: "memory");                     \
} while (0)

    ELOAD(0, 0);

    const int lr = (lane & 7) + (lane & 8);
    const int lc = (lane >> 4) << 3;

    for (int c = 0; c < 16; c++) {
        int buf = c & 1;
        if (c < 15) {
            ELOAD(c + 1, buf ^ 1);
            asm volatile("cp.async.wait_group 1;" ::: "memory");
        } else {
            asm volatile("cp.async.wait_group 0;" ::: "memory");
        }
        __syncthreads();
#pragma unroll
        for (int ks = 0; ks < 4; ks++) {
            int k0 = ks * 16;
            unsigned a[4];
            {
                unsigned addr = smem_u32(sA + buf * 128 * ESTR +
                                         (warp_m * 16 + lr) * ESTR + k0 + lc);
                ldm4(a[0], a[1], a[2], a[3], addr);
            }
            unsigned bb[8][2];
#pragma unroll
            for (int p = 0; p < 4; p++) {
                unsigned r0, r1, r2, r3;
                unsigned addr = smem_u32(sB + buf * 128 * ESTR +
                                         (warp_n * 64 + p * 16 + lr) * ESTR + k0 + lc);
                ldm4(r0, r1, r2, r3, addr);
                bb[2 * p][0] = r0; bb[2 * p + 1][0] = r1;
                bb[2 * p][1] = r2; bb[2 * p + 1][1] = r3;
            }
#pragma unroll
            for (int nt = 0; nt < 8; nt++)
                mma_fp16(acc[nt], a, bb[nt]);
        }
        __syncthreads();
    }

    /* epilogue: + b_enc, relu, store f32; zero out_topk (SCALAR stores —
       out_topk = d_out + 5 floats is only 4-byte aligned!) */
    const int crow = lane >> 2, ccol = (lane & 3) * 2;
    const int m1 = bm + warp_m * 16 + crow;
#pragma unroll
    for (int nt = 0; nt < 8; nt++) {
        int n = bn + warp_n * 64 + nt * 8 + ccol;
        float2 be = *(const float2*)&b_enc[n];
        float2 o1, o2;
        o1.x = fmaxf(acc[nt][0] + be.x, 0.f);
        o1.y = fmaxf(acc[nt][1] + be.y, 0.f);
        o2.x = fmaxf(acc[nt][2] + be.x, 0.f);
        o2.y = fmaxf(acc[nt][3] + be.y, 0.f);
        *(float2*)&g_acts[(size_t)m1 * S_N + n] = o1;
        *(float2*)&g_acts[(size_t)(m1 + 8) * S_N + n] = o2;
        outp[(size_t)m1 * S_N + n]           = 0.f;
        outp[(size_t)m1 * S_N + n + 1]       = 0.f;
        outp[(size_t)(m1 + 8) * S_N + n]     = 0.f;
        outp[(size_t)(m1 + 8) * S_N + n + 1] = 0.f;
    }
}

/* ------------------------- level-1 histogram ------------------------- */
__global__ void hist1_kernel() {
    __shared__ unsigned ha[4096];
    __shared__ unsigned hd[4096];
    for (int i = threadIdx.x; i < 4096; i += 256) { ha[i] = 0; hd[i] = 0; }
    __syncthreads();
    int t = blockIdx.x * 256 + threadIdx.x;
    const float4* A4 = (const float4*)g_acts;
    for (int r = 0; r < 30; r++) {
        int i4 = t + r * NTHR;
        float4 v = A4[i4];
        int cb = (i4 % SN4) * 4;
        uchar4 dd = *(const uchar4*)&g_dead[cb];
        float vv[4] = {v.x, v.y, v.z, v.w};
        unsigned char dm[4] = {dd.x, dd.y, dd.z, dd.w};
#pragma unroll
        for (int j = 0; j < 4; j++) {
            if (vv[j] > 0.f) {
                unsigned bin = __float_as_uint(vv[j]) >> 20;
                atomicAdd(&ha[bin], 1u);
                if (dm[j]) atomicAdd(&hd[bin], 1u);
            }
        }
    }
    __syncthreads();
    for (int i = threadIdx.x; i < 4096; i += 256) {
        if (ha[i]) atomicAdd(&g_hist_a[i], ha[i]);
        if (hd[i]) atomicAdd(&g_hist_d[i], hd[i]);
    }
}

__global__ void scan1_kernel() {
    if (threadIdx.x == 0) {
        unsigned long long cum = 0;
        for (int b = 4095; b >= 0; b--) {
            cum += g_hist_a[b];
            if (cum >= (unsigned long long)KTOP) {
                g_b1a = b; g_r1a = KTOP - (unsigned)(cum - g_hist_a[b]); break;
            }
        }
        cum = 0;
        for (int b = 4095; b >= 0; b--) {
            cum += g_hist_d[b];
            if (cum >= (unsigned long long)KAUX) {
                g_b1d = b; g_r1d = KAUX - (unsigned)(cum - g_hist_d[b]); break;
            }
        }
    }
    __syncthreads();
    for (int i = threadIdx.x; i < 4096; i += 256) { g_hist_a[i] = 0; g_hist_d[i] = 0; }
}

/* ------------------------- candidate compaction ------------------------- */
__device__ __forceinline__ void wappend(unsigned* buf, int* ctr, unsigned cap,
                                        bool pred, unsigned val) {
    unsigned m = __ballot_sync(0xffffffffu, pred);
    if (!m) return;
    int lane = threadIdx.x & 31;
    int leader = __ffs(m) - 1;
    int base = 0;
    if (lane == leader) base = atomicAdd(ctr, __popc(m));
    base = __shfl_sync(0xffffffffu, base, leader);
    if (pred) {
        int pos = base + __popc(m & ((1u << lane) - 1u));
        if ((unsigned)pos < cap) buf[pos] = val;
    }
}

__global__ void compact_kernel() {
    int t = blockIdx.x * 256 + threadIdx.x;
    const unsigned b1a = (unsigned)g_b1a, b1d = (unsigned)g_b1d;
    const float4* A4 = (const float4*)g_acts;
    for (int r = 0; r < 30; r++) {
        int i4 = t + r * NTHR;
        float4 v = A4[i4];
        int cb = (i4 % SN4) * 4;
        uchar4 dd = *(const uchar4*)&g_dead[cb];
        float vv[4] = {v.x, v.y, v.z, v.w};
        unsigned char dm[4] = {dd.x, dd.y, dd.z, dd.w};
#pragma unroll
        for (int j = 0; j < 4; j++) {
            unsigned u = __float_as_uint(vv[j]);
            bool pos = vv[j] > 0.f;
            wappend(g_cand_a, &g_nca, CANDCAP, pos && ((u >> 20) == b1a), u);
            wappend(g_cand_d, &g_ncd, CANDCAP, pos && dm[j] && ((u >> 20) == b1d), u);
        }
    }
}

/* ------------------------- level-2 refine + thresholds ------------------ */
__global__ void hist2_kernel() {
    __shared__ unsigned ha[4096];
    __shared__ unsigned hd[4096];
    for (int i = threadIdx.x; i < 4096; i += 256) { ha[i] = 0; hd[i] = 0; }
    __syncthreads();
    int stride = gridDim.x * 256;
    int t0 = blockIdx.x * 256 + threadIdx.x;
    int na = min(g_nca, (int)CANDCAP), nd = min(g_ncd, (int)CANDCAP);
    for (int i = t0; i < na; i += stride) atomicAdd(&ha[(g_cand_a[i] >> 8) & 0xFFF], 1u);
    for (int i = t0; i < nd; i += stride) atomicAdd(&hd[(g_cand_d[i] >> 8) & 0xFFF], 1u);
    __syncthreads();
    for (int i = threadIdx.x; i < 4096; i += 256) {
        if (ha[i]) atomicAdd(&g_hist_a[i], ha[i]);
        if (hd[i]) atomicAdd(&g_hist_d[i], hd[i]);
    }
}

__global__ void scan2_kernel() {
    if (threadIdx.x == 0) {
        unsigned long long cum = 0; unsigned K = g_r1a;
        for (int b = 4095; b >= 0; b--) {
            cum += g_hist_a[b];
            if (cum >= (unsigned long long)K) { g_b2a = b; break; }
        }
        cum = 0; K = g_r1d;
        for (int b = 4095; b >= 0; b--) {
            cum += g_hist_d[b];
            if (cum >= (unsigned long long)K) { g_b2d = b; break; }
        }
        g_tba = ((unsigned)g_b1a << 20) | ((unsigned)g_b2a << 8);
        g_tbd = ((unsigned)g_b1d << 20) | ((unsigned)g_b2d << 8);
        float t = __uint_as_float(g_tba);
        g_hib = __float_as_uint(t * (1.0f + 3.2e-3f));
        g_lob = __float_as_uint(t * (1.0f - 3.0e-3f));
    }
}

/* ------------------------- scatter (sparse commits) --------------------- */
__global__ void scatter_kernel(float* __restrict__ outp) {
    __shared__ float redf[256];
    __shared__ int redi[256];
    const unsigned hib = g_hib;
    const unsigned lob = g_lob;
    const float td = __uint_as_float(g_tbd);
    int t = blockIdx.x * 256 + threadIdx.x;
    float l1loc = 0.f;
    int l0loc = 0;
#pragma unroll 4
    for (int r = 0; r < 120; r++) {
        int i = t + r * NTHR;
        float v = g_acts[i];
        int row = i / S_N;
        int col = i - row * S_N;
        unsigned u = __float_as_uint(v);
        bool pos = v > 0.f;
        bool keep = pos && (u > hib);
        if (keep) {
            outp[i] = v;
            l1loc += v; l0loc++;
            int p = atomicAdd(&g_tcnt[row], 1);
            if (p < TOPCAP) {
                g_tcol[row * TOPCAP + p] = (unsigned short)col;
                g_tval[row * TOPCAP + p] = v;
            }
        }
        wappend((unsigned*)g_bidx, &g_nband, BANDCAP,
                pos && !keep && (u > lob), (unsigned)i);
        if (g_dead[col]) {
            float d = v - td;
            if (d > 0.f) {
                int p = atomicAdd(&g_acnt[row], 1);
                if (p < AUXCAP) {
                    g_acol[(size_t)row * AUXCAP + p] = (unsigned short)col;
                    g_aval[(size_t)row * AUXCAP + p] = d;
                }
            }
        }
    }
    redf[threadIdx.x] = l1loc;
    redi[threadIdx.x] = l0loc;
    __syncthreads();
    for (int s = 128; s > 0; s >>= 1) {
        if (threadIdx.x < s) {
            redf[threadIdx.x] += redf[threadIdx.x + s];
            redi[threadIdx.x] += redi[threadIdx.x + s];
        }
        __syncthreads();
    }
    if (threadIdx.x == 0) {
        atomicAdd(&g_l1s, (double)redf[0]);
        atomicAdd(&g_l0s, (unsigned long long)redi[0]);
        atomicAdd(&g_nhi, redi[0]);
    }
}

/* ------------------------- exact dot (double-f32, coalesced WTe) -------- */
__device__ __forceinline__ void exact_dot(int row, int col, int lane,
                                          float& sh_out, float& sl_out) {
    const float* xr = &g_xc[row * D_N];
    const float* wr = &g_WTe[(size_t)col * D_N];
    float sh = 0.f, sl = 0.f;
#pragma unroll 4
    for (int j = 0; j < 32; j++) {
        int k = lane + j * 32;
        float a = xr[k], b = wr[k];
        float ph = fmul_rn(a, b);
        float pl = ffma_rn(a, b, -ph);
        float s  = fadd_rn(sh, ph);
        float bb = fsub_rn(s, sh);
        float e1 = fsub_rn(sh, fsub_rn(s, bb));
        float e2 = fsub_rn(ph, bb);
        sh = s;
        sl = fadd_rn(sl, fadd_rn(fadd_rn(e1, e2), pl));
    }
    for (int off = 16; off; off >>= 1) {
        float oh = __shfl_down_sync(0xffffffffu, sh, off);
        float ol = __shfl_down_sync(0xffffffffu, sl, off);
        float s  = fadd_rn(sh, oh);
        float bb = fsub_rn(s, sh);
        float e1 = fsub_rn(sh, fsub_rn(s, bb));
        float e2 = fsub_rn(oh, bb);
        sh = s;
        sl = fadd_rn(sl, fadd_rn(fadd_rn(e1, e2), ol));
    }
    sh_out = sh; sl_out = sl;
}

/* exact band dots */
__global__ void band_dot_kernel(const float* __restrict__ b_enc) {
    int w = (blockIdx.x * 256 + threadIdx.x) >> 5;
    int lane = threadIdx.x & 31;
    int nb = min(g_nband, (int)BANDCAP);
    if (w >= nb) return;
    int idx = g_bidx[w];
    int row = idx / S_N, col = idx - row * S_N;
    float sh, sl;
    exact_dot(row, col, lane, sh, sl);
    if (lane == 0) {
        double val = (double)sh + (double)sl + (double)b_enc[col];
        float hh = (float)val;
        g_bhi[w] = hh;
        g_blo[w] = (float)(val - (double)hh);
    }
}

/* ------------------------- band ranking + commit (16K bitonic) -------- */
__global__ __launch_bounds__(1024) void band_rank_kernel(float* __restrict__ outp) {
    extern __shared__ char bsm[];
    double* sval = (double*)bsm;
    int*    sidx = (int*)(bsm + (size_t)BANDCAP * 8);
    __shared__ double rsm[32];
    int tid = threadIdx.x;
    int nb = min(g_nband, (int)BANDCAP);
    for (int i = tid; i < BANDCAP; i += 1024) {
        if (i < nb) {
            sval[i] = (double)g_bhi[i] + (double)g_blo[i];
            sidx[i] = g_bidx[i];
        } else {
            sval[i] = -1e300;
            sidx[i] = 0x7fffffff;
        }
    }
    __syncthreads();
    for (int size = 2; size <= BANDCAP; size <<= 1) {
        for (int stride = size >> 1; stride; stride >>= 1) {
            for (int i = tid; i < BANDCAP / 2; i += 1024) {
                int pos = 2 * i - (i & (stride - 1));
                int a = pos, b = pos + stride;
                bool dirDesc = ((pos & size) == 0);
                bool agtb = (sval[a] != sval[b]) ? (sval[a] > sval[b])
                                                 : (sidx[a] < sidx[b]);
                if (dirDesc ? !agtb : agtb) {
                    double tv = sval[a]; sval[a] = sval[b]; sval[b] = tv;
                    int ti = sidx[a]; sidx[a] = sidx[b]; sidx[b] = ti;
                }
            }
            __syncthreads();
        }
    }
    int needK = (int)KTOP - g_nhi;
    if (needK < 0) needK = 0;
    if (needK > nb) needK = nb;
    double l1loc = 0.0;
    for (int i = tid; i < needK; i += 1024) {
        int idx = sidx[i];
        float fv = (float)sval[i];
        outp[idx] = fv;
        int row = idx / S_N, col = idx - row * S_N;
        int p = atomicAdd(&g_tcnt[row], 1);
        if (p < TOPCAP) {
            g_tcol[row * TOPCAP + p] = (unsigned short)col;
            g_tval[row * TOPCAP + p] = fv;
        }
        l1loc += (double)fv;
    }
    for (int off = 16; off; off >>= 1)
        l1loc += __shfl_down_sync(0xffffffffu, l1loc, off);
    if ((tid & 31) == 0) rsm[tid >> 5] = l1loc;
    __syncthreads();
    if (tid == 0) {
        double s = 0.0;
        for (int q = 0; q < 32; q++) s += rsm[q];
        atomicAdd(&g_l1s, s);
        atomicAdd(&g_l0s, (unsigned long long)needK);
    }
}

/* ------------------------- sparse Matryoshka decode ------------------------- */
__global__ void decode_kernel(const float* __restrict__ x,
                              const float* __restrict__ b_dec,
                              const float* __restrict__ W_dec,
                              float* __restrict__ out_recon)
{
    __shared__ unsigned short scol[TOPCAP];
    __shared__ float sval[TOPCAP];
    __shared__ float red[256];
    int row = blockIdx.x, tid = threadIdx.x;
    int cnt = min(g_tcnt[row], TOPCAP);
    for (int i = tid; i < cnt; i += 256) {
        scol[i] = g_tcol[row * TOPCAP + i];
        sval[i] = g_tval[row * TOPCAP + i];
    }
    __syncthreads();
    int d = tid * 4;
    float4 acc = *(const float4*)&b_dec[d];
    float4 xv = *(const float4*)&x[row * D_N + d];
    const int bounds[5] = {0, 2048, 6144, 14336, 30720};
#pragma unroll
    for (int g = 0; g < 4; g++) {
        int lo = bounds[g], hi = bounds[g + 1];
        for (int e = 0; e < cnt; e++) {
            int c = scol[e];
            if (c >= lo && c < hi) {
                float vv = sval[e];
                float4 w = *(const float4*)&W_dec[(size_t)c * D_N + d];
                acc.x += vv * w.x; acc.y += vv * w.y;
                acc.z += vv * w.z; acc.w += vv * w.w;
            }
        }
        float dx = acc.x - xv.x, dy = acc.y - xv.y;
        float dz = acc.z - xv.z, dw = acc.w - xv.w;
        red[tid] = dx * dx + dy * dy + dz * dz + dw * dw;
        __syncthreads();
        for (int s = 128; s > 0; s >>= 1) {
            if (tid < s) red[tid] += red[tid + s];
            __syncthreads();
        }
        if (tid == 0) atomicAdd(&g_l2s[g], (double)red[0]);
        __syncthreads();
    }
    float* ro = out_recon + (size_t)row * D_N + d;
    ro[0] = acc.x; ro[1] = acc.y; ro[2] = acc.z; ro[3] = acc.w;
    *(float4*)&g_recon[row * D_N + d] = acc;
}

/* ------------------------- aux dense GEMM (smem + ldmatrix + mma.sync) ------- */
#define KCH 32
#define SSTR 40
__global__ __launch_bounds__(256) void aux_gemm(const float* __restrict__ x)
{
    __shared__ __align__(16) __nv_bfloat16 sA[2][128][SSTR];
    __shared__ __align__(16) __nv_bfloat16 sB[2][128][SSTR];
    __shared__ float wsum[8];

    if (g_ndead == 0) return;
    const int pad = g_ndead_pad;
    const int nchunks = pad / KCH;
    const int tid = threadIdx.x;
    const int wid = tid >> 5;
    const int lane = tid & 31;
    const int warp_m = wid & 3;
    const int warp_n = wid >> 2;
    const int bm = blockIdx.x * 128;
    const int bn = blockIdx.y * 128;
    const int m0 = bm + warp_m * 32;
    const int n0l = warp_n * 64;

    float acc[2][8][4];
#pragma unroll
    for (int mt = 0; mt < 2; mt++)
#pragma unroll
        for (int nt = 0; nt < 8; nt++)
#pragma unroll
            for (int q = 0; q < 4; q++) acc[mt][nt][q] = 0.f;

    const int lrow = tid >> 1;
    const int lseg = tid & 1;

#define LOAD_CHUNK(c, b)                                                        \
    do {                                                                        \
        int kof = (c) * KCH;                                                    \
        cp16(smem_u32(&sA[b][lrow][(lseg) * 8]),                                \
             &g_A[(size_t)(bm + lrow) * pad + kof + (lseg) * 8]);               \
        cp16(smem_u32(&sA[b][lrow][(lseg + 2) * 8]),                            \
             &g_A[(size_t)(bm + lrow) * pad + kof + (lseg + 2) * 8]);           \
        cp16(smem_u32(&sB[b][lrow][(lseg) * 8]),                                \
             &g_WT[(size_t)(bn + lrow) * pad + kof + (lseg) * 8]);              \
        cp16(smem_u32(&sB[b][lrow][(lseg + 2) * 8]),                            \
             &g_WT[(size_t)(bn + lrow) * pad + kof + (lseg + 2) * 8]);          \
        asm volatile("cp.async.commit_group;" ::: "memory");                    \
    } while (0)

    LOAD_CHUNK(0, 0);

    const int lr = (lane & 7) + (lane & 8);
    const int lc = (lane >> 4) << 3;

    for (int c = 0; c < nchunks; c++) {
        int buf = c & 1;
        if (c + 1 < nchunks) {
            LOAD_CHUNK(c + 1, (c + 1) & 1);
            asm volatile("cp.async.wait_group 1;" ::: "memory");
        } else {
            asm volatile("cp.async.wait_group 0;" ::: "memory");
        }
        __syncthreads();

#pragma unroll
        for (int ks = 0; ks < KCH / 16; ks++) {
            int k0 = ks * 16;
            unsigned a[2][4];
#pragma unroll
            for (int mt = 0; mt < 2; mt++) {
                unsigned addr = smem_u32(&sA[buf][warp_m * 32 + mt * 16 + lr][k0 + lc]);
                ldm4(a[mt][0], a[mt][1], a[mt][2], a[mt][3], addr);
            }
            unsigned bb[8][2];
#pragma unroll
            for (int p = 0; p < 4; p++) {
                unsigned r0, r1, r2, r3;
                unsigned addr = smem_u32(&sB[buf][n0l + p * 16 + lr][k0 + lc]);
                ldm4(r0, r1, r2, r3, addr);
                bb[2 * p][0] = r0; bb[2 * p + 1][0] = r1;
                bb[2 * p][1] = r2; bb[2 * p + 1][1] = r3;
            }
#pragma unroll
            for (int mt = 0; mt < 2; mt++)
#pragma unroll
                for (int nt = 0; nt < 8; nt++)
                    mma_bf16(acc[mt][nt], a[mt], bb[nt]);
        }
        __syncthreads();
    }

    const int crow = lane >> 2;
    const int ccol = (lane & 3) * 2;
    const int n0 = bn + n0l;
    float sum = 0.f;
#pragma unroll
    for (int mt = 0; mt < 2; mt++) {
#pragma unroll
        for (int nt = 0; nt < 8; nt++) {
            int m1 = m0 + mt * 16 + crow;
            int m2 = m1 + 8;
            int dd = n0 + nt * 8 + ccol;
            float2 xv1 = *(const float2*)&x[(size_t)m1 * D_N + dd];
            float2 rv1 = *(const float2*)&g_recon[(size_t)m1 * D_N + dd];
            float2 xv2 = *(const float2*)&x[(size_t)m2 * D_N + dd];
            float2 rv2 = *(const float2*)&g_recon[(size_t)m2 * D_N + dd];
            float d0 = acc[mt][nt][0] - (xv1.x - rv1.x);
            float d1 = acc[mt][nt][1] - (xv1.y - rv1.y);
            float d2 = acc[mt][nt][2] - (xv2.x - rv2.x);
            float d3 = acc[mt][nt][3] - (xv2.y - rv2.y);
            sum += d0 * d0 + d1 * d1 + d2 * d2 + d3 * d3;
        }
    }
    for (int off = 16; off; off >>= 1)
        sum += __shfl_down_sync(0xffffffffu, sum, off);
    if (lane == 0) wsum[wid] = sum;
    __syncthreads();
    if (tid == 0) {
        float s = 0.f;
        for (int w = 0; w < 8; w++) s += wsum[w];
        atomicAdd(&g_auxs, (double)s);
    }
}

/* ------------------------- finalize ------------------------- */
__global__ void fin_kernel(float* __restrict__ out) {
    double inv = 1.0 / ((double)B_N * (double)D_N);
    double l2m = (g_l2s[0] + g_l2s[1] + g_l2s[2] + g_l2s[3]) * 0.25 * inv;
    double l1 = 1e-3 * g_l1s / (double)B_N;
    double l0 = (double)g_l0s / (double)B_N;
    double aux = g_any_dead ? (1e-2 * g_auxs * inv) : 0.0;
    out[0] = (float)(l2m + l1 + aux);
    out[1] = (float)l2m;
    out[2] = (float)l1;
    out[3] = (float)aux;
    out[4] = (float)l0;
}

/* ------------------------- launch ------------------------- */
extern "C" void kernel_launch(void* const* d_in, const int* in_sizes, int n_in,
                              void* d_out, int out_size) {
    const float* x     = (const float*)d_in[0];
    const float* b_dec = (const float*)d_in[1];
    const float* b_enc = (const float*)d_in[2];
    const float* W_enc = (const float*)d_in[3];
    const float* W_dec = (const float*)d_in[4];
    const int*   nbna  = (const int*)d_in[5];
    float* out = (float*)d_out;
    float* out_topk  = out + 5;
    float* out_recon = out + 5 + (size_t)B_N * S_N;

    static int attrs_set = 0;
    if (!attrs_set) {
        cudaFuncSetAttribute(enc_mma, cudaFuncAttributeMaxDynamicSharedMemorySize,
                             4 * 128 * ESTR * 2);
        cudaFuncSetAttribute(band_rank_kernel,
                             cudaFuncAttributeMaxDynamicSharedMemorySize,
                             BANDCAP * 12);
        attrs_set = 1;
    }

    reset_kernel<<<(S_N + 255) / 256, 256>>>(nbna);
    dm1_kernel<<<30, 1024>>>();
    dm2_kernel<<<1, 1>>>();
    dm3_kernel<<<30, 1024>>>();
    zeroA_kernel<<<2048, 256>>>();
    wtT_kernel<<<dim3(S_N / 64, D_N / 64), 256>>>(W_dec);
    sub_kernel<<<B_N * D_N / 4 / 256, 256>>>(x, b_dec);
    whl_kernel<<<dim3(S_N / 64, D_N / 64), 256>>>(W_enc);
    enc_mma<<<dim3(B_N / 128, S_N / 128), 512, 4 * 128 * ESTR * 2>>>(b_enc, out_topk);
    hist1_kernel<<<2048, 256>>>();
    scan1_kernel<<<1, 256>>>();
    compact_kernel<<<2048, 256>>>();
    hist2_kernel<<<512, 256>>>();
    scan2_kernel<<<1, 256>>>();
    scatter_kernel<<<2048, 256>>>(out_topk);
    band_dot_kernel<<<BANDCAP / 8, 256>>>(b_enc);
    band_rank_kernel<<<1, 1024, BANDCAP * 12>>>(out_topk);
    Ascatter_kernel<<<B_N, 256>>>();
    decode_kernel<<<B_N, 256>>>(x, b_dec, W_dec, out_recon);
    aux_gemm<<<dim3(B_N / 128, D_N / 128), 256>>>(x);
    fin_kernel<<<1, 1>>>(out);
}

// round 15
// speedup vs baseline: 1.4154x; 1.2843x over previous
#include <cuda_runtime.h>
#include <cuda_bf16.h>
#include <cuda_fp16.h>
#include <cstdint>

#define B_N   2048
#define D_N   1024
#define S_N   30720
#define SN4   7680
#define NTHR  524288
#define KTOP  131072u
#define KAUX  2097152u
#define TOPCAP 160
#define AUXCAP 2048
#define BANDCAP 16384
#define CANDCAP (4u<<20)

/* ------------------------- scratch ------------------------- */
__device__ float g_acts[(size_t)B_N * S_N];
__device__ float g_xc[B_N * D_N];
__device__ float g_recon[B_N * D_N];
__device__ unsigned g_hist_a[4096];
__device__ unsigned g_hist_d[4096];
__device__ unsigned char g_dead[S_N];
__device__ int g_any_dead;
__device__ int g_b1a, g_b1d, g_b2a, g_b2d;
__device__ unsigned g_r1a, g_r1d;
__device__ unsigned g_tba, g_tbd;
__device__ unsigned g_hib, g_lob;
__device__ int g_bidx[BANDCAP];
__device__ float g_bhi[BANDCAP], g_blo[BANDCAP];
__device__ int g_nband, g_nhi;
__device__ unsigned short g_tcol[B_N * TOPCAP];
__device__ float          g_tval[B_N * TOPCAP];
__device__ int            g_tcnt[B_N];
__device__ unsigned short g_acol[(size_t)B_N * AUXCAP];
__device__ float          g_aval[(size_t)B_N * AUXCAP];
__device__ int            g_acnt[B_N];
__device__ double g_l2s[4];
__device__ double g_l1s;
__device__ unsigned long long g_l0s;
__device__ double g_auxs;

/* encoder fp16 GEMM scratch */
__device__ __half g_xhi[B_N * D_N];
__device__ __half g_Whi[(size_t)S_N * D_N];          /* W_enc^T fp16 [n][k] */
__device__ float  g_WTe[(size_t)S_N * D_N];          /* W_enc^T exact f32 [n][k] */

/* dense aux GEMM scratch */
__device__ __nv_bfloat16 g_A[(size_t)B_N * S_N];
__device__ __nv_bfloat16 g_WT[(size_t)D_N * S_N];
__device__ int g_dmap[S_N];
__device__ int g_dinv[S_N];
__device__ int g_dcnt[32];
__device__ int g_ndead, g_ndead_pad;

/* ------------------------- exact f32 helpers ------------------------- */
__device__ __forceinline__ float fadd_rn(float a, float b) {
    float r; asm("add.rn.f32 %0, %1, %2;" : "=f"(r) : "f"(a), "f"(b)); return r;
}
__device__ __forceinline__ float fsub_rn(float a, float b) {
    float r; asm("sub.rn.f32 %0, %1, %2;" : "=f"(r) : "f"(a), "f"(b)); return r;
}
__device__ __forceinline__ float fmul_rn(float a, float b) {
    float r; asm("mul.rn.f32 %0, %1, %2;" : "=f"(r) : "f"(a), "f"(b)); return r;
}
__device__ __forceinline__ float ffma_rn(float a, float b, float c) {
    float r; asm("fma.rn.f32 %0, %1, %2, %3;" : "=f"(r) : "f"(a), "f"(b), "f"(c)); return r;
}

/* mma.sync bf16 / fp16 (baseline PTX, plain sm_103) */
__device__ __forceinline__ void mma_bf16(float* c, const unsigned* a, const unsigned* b) {
    asm volatile(
        "mma.sync.aligned.m16n8k16.row.col.f32.bf16.bf16.f32 "
        "{%0,%1,%2,%3}, {%4,%5,%6,%7}, {%8,%9}, {%0,%1,%2,%3};"
        : "+f"(c[0]), "+f"(c[1]), "+f"(c[2]), "+f"(c[3])
        : "r"(a[0]), "r"(a[1]), "r"(a[2]), "r"(a[3]), "r"(b[0]), "r"(b[1]));
}
__device__ __forceinline__ void mma_fp16(float* c, const unsigned* a, const unsigned* b) {
    asm volatile(
        "mma.sync.aligned.m16n8k16.row.col.f32.f16.f16.f32 "
        "{%0,%1,%2,%3}, {%4,%5,%6,%7}, {%8,%9}, {%0,%1,%2,%3};"
        : "+f"(c[0]), "+f"(c[1]), "+f"(c[2]), "+f"(c[3])
        : "r"(a[0]), "r"(a[1]), "r"(a[2]), "r"(a[3]), "r"(b[0]), "r"(b[1]));
}
__device__ __forceinline__ uint32_t smem_u32(const void* p) {
    uint32_t a;
    asm("{ .reg .u64 t; cvta.to.shared.u64 t, %1; cvt.u32.u64 %0, t; }"
        : "=r"(a) : "l"(p));
    return a;
}
__device__ __forceinline__ void ldm4(unsigned &r0, unsigned &r1,
                                     unsigned &r2, unsigned &r3, unsigned addr) {
    asm volatile("ldmatrix.sync.aligned.m8n8.x4.shared.b16 {%0,%1,%2,%3}, [%4];"
                 : "=r"(r0), "=r"(r1), "=r"(r2), "=r"(r3) : "r"(addr));
}
__device__ __forceinline__ void cp16(unsigned saddr, const void* gptr) {
    asm volatile("cp.async.cg.shared.global [%0], [%1], 16;"
                 :: "r"(saddr), "l"(gptr) : "memory");
}

/* ------------------------- setup ------------------------- */
__global__ void reset_kernel(const int* __restrict__ nbna) {
    int i = blockIdx.x * 256 + threadIdx.x;
    if (i == 0) {
        g_nband = 0; g_nhi = 0;
        g_l1s = 0.0; g_l0s = 0ull; g_auxs = 0.0; g_any_dead = 0;
        g_l2s[0] = g_l2s[1] = g_l2s[2] = g_l2s[3] = 0.0;
    }
    if (i < 4096) { g_hist_a[i] = 0; g_hist_d[i] = 0; }
    if (i < B_N) { g_tcnt[i] = 0; g_acnt[i] = 0; }
    if (i < S_N) {
        unsigned char d = (nbna[i] >= 20) ? 1 : 0;
        g_dead[i] = d;
        if (d) g_any_dead = 1;
    }
}

/* dead-feature dense mapping */
__global__ void dm1_kernel() {
    __shared__ int red[1024];
    int i = blockIdx.x * 1024 + threadIdx.x;
    red[threadIdx.x] = g_dead[i] ? 1 : 0;
    __syncthreads();
    for (int s = 512; s > 0; s >>= 1) {
        if (threadIdx.x < s) red[threadIdx.x] += red[threadIdx.x + s];
        __syncthreads();
    }
    if (threadIdx.x == 0) g_dcnt[blockIdx.x] = red[0];
}
__global__ void dm2_kernel() {
    int run = 0;
    for (int b = 0; b < 30; b++) {
        int c = g_dcnt[b];
        g_dcnt[b] = run;
        run += c;
    }
    g_ndead = run;
    g_ndead_pad = (run + 63) & ~63;
}
__global__ void dm3_kernel() {
    __shared__ int sc[1024];
    int i = blockIdx.x * 1024 + threadIdx.x;
    int f = g_dead[i] ? 1 : 0;
    sc[threadIdx.x] = f;
    __syncthreads();
    for (int off = 1; off < 1024; off <<= 1) {
        int v = (threadIdx.x >= off) ? sc[threadIdx.x - off] : 0;
        __syncthreads();
        sc[threadIdx.x] += v;
        __syncthreads();
    }
    if (f) {
        int dense = g_dcnt[blockIdx.x] + sc[threadIdx.x] - 1;
        g_dmap[i] = dense;
        g_dinv[dense] = i;
    }
}

__global__ void zeroA_kernel() {
    size_t tot = (size_t)B_N * (size_t)g_ndead_pad / 4;
    uint2 z = {0u, 0u};
    uint2* p = (uint2*)g_A;
    size_t stride = (size_t)gridDim.x * blockDim.x;
    for (size_t i = blockIdx.x * (size_t)blockDim.x + threadIdx.x; i < tot; i += stride)
        p[i] = z;
}

/* W_dec^T (dead cols) bf16 tiled transpose */
__global__ void wtT_kernel(const float* __restrict__ W_dec) {
    __shared__ float tile[64][65];
    int pad = g_ndead_pad;
    int nd  = g_ndead;
    int j0 = blockIdx.x * 64;
    if (j0 >= pad) return;
    int d0 = blockIdx.y * 64;
    int t = threadIdx.x;
#pragma unroll
    for (int s = 0; s < 16; s++) {
        int idx = t + s * 256;
        int jl = idx >> 6, dl = idx & 63;
        int j = j0 + jl;
        float v = 0.f;
        if (j < nd) v = W_dec[(size_t)g_dinv[j] * D_N + d0 + dl];
        tile[jl][dl] = v;
    }
    __syncthreads();
#pragma unroll
    for (int s = 0; s < 16; s++) {
        int idx = t + s * 256;
        int dl = idx >> 6, jl = idx & 63;
        g_WT[(size_t)(d0 + dl) * pad + j0 + jl] = __float2bfloat16(tile[jl][dl]);
    }
}

/* W_enc transpose: [k][n] f32 -> [n][k] f32 exact + fp16 */
__global__ void whl_kernel(const float* __restrict__ W) {
    __shared__ float tile[64][65];
    int n0 = blockIdx.x * 64;
    int k0 = blockIdx.y * 64;
    int t = threadIdx.x;
#pragma unroll
    for (int s = 0; s < 16; s++) {
        int idx = t + s * 256;
        int kl = idx >> 6, nl = idx & 63;
        tile[kl][nl] = W[(size_t)(k0 + kl) * S_N + n0 + nl];
    }
    __syncthreads();
#pragma unroll
    for (int s = 0; s < 16; s++) {
        int idx = t + s * 256;
        int nl = idx >> 6, kl = idx & 63;
        float v = tile[kl][nl];
        g_WTe[(size_t)(n0 + nl) * D_N + k0 + kl] = v;
        g_Whi[(size_t)(n0 + nl) * D_N + k0 + kl] = __float2half_rn(v);
    }
}

/* scatter COO aux values into dense bf16 A */
__global__ void Ascatter_kernel() {
    int row = blockIdx.x;
    int pad = g_ndead_pad;
    int cnt = min(g_acnt[row], AUXCAP);
    for (int i = threadIdx.x; i < cnt; i += 256) {
        int col = g_acol[(size_t)row * AUXCAP + i];
        float v = g_aval[(size_t)row * AUXCAP + i];
        g_A[(size_t)row * pad + g_dmap[col]] = __float2bfloat16(v);
    }
}

/* xc = x - b_dec  (f32 + fp16) */
__global__ void sub_kernel(const float* __restrict__ x,
                           const float* __restrict__ b_dec) {
    int i = blockIdx.x * 256 + threadIdx.x;
    float4 xv = ((const float4*)x)[i];
    float4 bv = ((const float4*)b_dec)[i & 255];
    float4 o;
    o.x = xv.x - bv.x; o.y = xv.y - bv.y;
    o.z = xv.z - bv.z; o.w = xv.w - bv.w;
    ((float4*)g_xc)[i] = o;
    ((__half2*)g_xhi)[i * 2]     = __floats2half2_rn(o.x, o.y);
    ((__half2*)g_xhi)[i * 2 + 1] = __floats2half2_rn(o.z, o.w);
}

/* ------------- encoder GEMM (fp16 mma.sync) ---------- */
#define EKCH 64
#define ESTR 72
__global__ __launch_bounds__(512) void enc_mma(const float* __restrict__ b_enc)
{
    extern __shared__ __half esm[];
    __half* sA = esm;                    /* [2][128][ESTR] */
    __half* sB = esm + 2 * 128 * ESTR;

    const int tid = threadIdx.x;
    const int wid = tid >> 5, lane = tid & 31;
    const int warp_m = wid & 7;
    const int warp_n = wid >> 3;
    const int bm = blockIdx.x * 128;
    const int bn = blockIdx.y * 128;

    float acc[8][4];
#pragma unroll
    for (int nt = 0; nt < 8; nt++)
#pragma unroll
        for (int q = 0; q < 4; q++) acc[nt][q] = 0.f;

    const int lrow = tid >> 2;
    const int lcol = (tid & 3) * 16;

#define ELOAD(c, b) do {                                                     \
    int kof = (c) * EKCH + lcol;                                             \
    const __half* gA = &g_xhi[(size_t)(bm + lrow) * D_N + kof];              \
    const __half* gB = &g_Whi[(size_t)(bn + lrow) * D_N + kof];              \
    unsigned dA = smem_u32(sA + (b) * 128 * ESTR + lrow * ESTR + lcol);      \
    unsigned dB = smem_u32(sB + (b) * 128 * ESTR + lrow * ESTR + lcol);      \
    cp16(dA, gA); cp16(dA + 16, gA + 8);                                     \
    cp16(dB, gB); cp16(dB + 16, gB + 8);                                     \
    asm volatile("cp.async.commit_group;" ::: "memory");                     \
} while (0)

    ELOAD(0, 0);

    const int lr = (lane & 7) + (lane & 8);
    const int lc = (lane >> 4) << 3;

    for (int c = 0; c < 16; c++) {
        int buf = c & 1;
        if (c < 15) {
            ELOAD(c + 1, buf ^ 1);
            asm volatile("cp.async.wait_group 1;" ::: "memory");
        } else {
            asm volatile("cp.async.wait_group 0;" ::: "memory");
        }
        __syncthreads();
#pragma unroll
        for (int ks = 0; ks < 4; ks++) {
            int k0 = ks * 16;
            unsigned a[4];
            {
                unsigned addr = smem_u32(sA + buf * 128 * ESTR +
                                         (warp_m * 16 + lr) * ESTR + k0 + lc);
                ldm4(a[0], a[1], a[2], a[3], addr);
            }
            unsigned bb[8][2];
#pragma unroll
            for (int p = 0; p < 4; p++) {
                unsigned r0, r1, r2, r3;
                unsigned addr = smem_u32(sB + buf * 128 * ESTR +
                                         (warp_n * 64 + p * 16 + lr) * ESTR + k0 + lc);
                ldm4(r0, r1, r2, r3, addr);
                bb[2 * p][0] = r0; bb[2 * p + 1][0] = r1;
                bb[2 * p][1] = r2; bb[2 * p + 1][1] = r3;
            }
#pragma unroll
            for (int nt = 0; nt < 8; nt++)
                mma_fp16(acc[nt], a, bb[nt]);
        }
        __syncthreads();
    }

    /* epilogue: + b_enc, relu, store f32 */
    const int crow = lane >> 2, ccol = (lane & 3) * 2;
    const int m1 = bm + warp_m * 16 + crow;
#pragma unroll
    for (int nt = 0; nt < 8; nt++) {
        int n = bn + warp_n * 64 + nt * 8 + ccol;
        float2 be = *(const float2*)&b_enc[n];
        float2 o1, o2;
        o1.x = fmaxf(acc[nt][0] + be.x, 0.f);
        o1.y = fmaxf(acc[nt][1] + be.y, 0.f);
        o2.x = fmaxf(acc[nt][2] + be.x, 0.f);
        o2.y = fmaxf(acc[nt][3] + be.y, 0.f);
        *(float2*)&g_acts[(size_t)m1 * S_N + n] = o1;
        *(float2*)&g_acts[(size_t)(m1 + 8) * S_N + n] = o2;
    }
}

/* ------------------------- level-1 histogram ------------------------- */
__global__ void hist1_kernel() {
    __shared__ unsigned ha[4096];
    __shared__ unsigned hd[4096];
    for (int i = threadIdx.x; i < 4096; i += 256) { ha[i] = 0; hd[i] = 0; }
    __syncthreads();
    int t = blockIdx.x * 256 + threadIdx.x;
    const float4* A4 = (const float4*)g_acts;
    for (int r = 0; r < 30; r++) {
        int i4 = t + r * NTHR;
        float4 v = A4[i4];
        int cb = (i4 % SN4) * 4;
        uchar4 dd = *(const uchar4*)&g_dead[cb];
        float vv[4] = {v.x, v.y, v.z, v.w};
        unsigned char dm[4] = {dd.x, dd.y, dd.z, dd.w};
#pragma unroll
        for (int j = 0; j < 4; j++) {
            if (vv[j] > 0.f) {
                unsigned bin = __float_as_uint(vv[j]) >> 20;
                atomicAdd(&ha[bin], 1u);
                if (dm[j]) atomicAdd(&hd[bin], 1u);
            }
        }
    }
    __syncthreads();
    for (int i = threadIdx.x; i < 4096; i += 256) {
        if (ha[i]) atomicAdd(&g_hist_a[i], ha[i]);
        if (hd[i]) atomicAdd(&g_hist_d[i], hd[i]);
    }
}

__global__ void scan1_kernel() {
    if (threadIdx.x == 0) {
        unsigned long long cum = 0;
        for (int b = 4095; b >= 0; b--) {
            cum += g_hist_a[b];
            if (cum >= (unsigned long long)KTOP) {
                g_b1a = b; g_r1a = KTOP - (unsigned)(cum - g_hist_a[b]); break;
            }
        }
        cum = 0;
        for (int b = 4095; b >= 0; b--) {
            cum += g_hist_d[b];
            if (cum >= (unsigned long long)KAUX) {
                g_b1d = b; g_r1d = KAUX - (unsigned)(cum - g_hist_d[b]); break;
            }
        }
    }
    __syncthreads();
    for (int i = threadIdx.x; i < 4096; i += 256) { g_hist_a[i] = 0; g_hist_d[i] = 0; }
}

/* ------------------- level-2 histogram fused (reads g_acts) ------------- */
__global__ void l2hist_kernel() {
    __shared__ unsigned ha[4096];
    __shared__ unsigned hd[4096];
    for (int i = threadIdx.x; i < 4096; i += 256) { ha[i] = 0; hd[i] = 0; }
    __syncthreads();
    int t = blockIdx.x * 256 + threadIdx.x;
    const unsigned b1a = (unsigned)g_b1a, b1d = (unsigned)g_b1d;
    const float4* A4 = (const float4*)g_acts;
    for (int r = 0; r < 30; r++) {
        int i4 = t + r * NTHR;
        float4 v = A4[i4];
        int cb = (i4 % SN4) * 4;
        uchar4 dd = *(const uchar4*)&g_dead[cb];
        float vv[4] = {v.x, v.y, v.z, v.w};
        unsigned char dm[4] = {dd.x, dd.y, dd.z, dd.w};
#pragma unroll
        for (int j = 0; j < 4; j++) {
            unsigned u = __float_as_uint(vv[j]);
            bool pos = vv[j] > 0.f;
            if (pos && ((u >> 20) == b1a)) atomicAdd(&ha[(u >> 8) & 0xFFF], 1u);
            if (pos && dm[j] && ((u >> 20) == b1d)) atomicAdd(&hd[(u >> 8) & 0xFFF], 1u);
        }
    }
    __syncthreads();
    for (int i = threadIdx.x; i < 4096; i += 256) {
        if (ha[i]) atomicAdd(&g_hist_a[i], ha[i]);
        if (hd[i]) atomicAdd(&g_hist_d[i], hd[i]);
    }
}

__global__ void scan2_kernel() {
    if (threadIdx.x == 0) {
        unsigned long long cum = 0; unsigned K = g_r1a;
        for (int b = 4095; b >= 0; b--) {
            cum += g_hist_a[b];
            if (cum >= (unsigned long long)K) { g_b2a = b; break; }
        }
        cum = 0; K = g_r1d;
        for (int b = 4095; b >= 0; b--) {
            cum += g_hist_d[b];
            if (cum >= (unsigned long long)K) { g_b2d = b; break; }
        }
        g_tba = ((unsigned)g_b1a << 20) | ((unsigned)g_b2a << 8);
        g_tbd = ((unsigned)g_b1d << 20) | ((unsigned)g_b2d << 8);
        float t = __uint_as_float(g_tba);
        g_hib = __float_as_uint(t * (1.0f + 3.2e-3f));
        g_lob = __float_as_uint(t * (1.0f - 3.0e-3f));
    }
}

/* ------------------------- candidate append helper ---------------------- */
__device__ __forceinline__ void wappend(unsigned* buf, int* ctr, unsigned cap,
                                        bool pred, unsigned val) {
    unsigned m = __ballot_sync(0xffffffffu, pred);
    if (!m) return;
    int lane = threadIdx.x & 31;
    int leader = __ffs(m) - 1;
    int base = 0;
    if (lane == leader) base = atomicAdd(ctr, __popc(m));
    base = __shfl_sync(0xffffffffu, base, leader);
    if (pred) {
        int pos = base + __popc(m & ((1u << lane) - 1u));
        if ((unsigned)pos < cap) buf[pos] = val;
    }
}

/* ------------------------- scatter (commit values) ---------------------- */
__global__ void scatter_kernel(float* __restrict__ outp) {
    __shared__ float redf[256];
    __shared__ int redi[256];
    const unsigned hib = g_hib;
    const unsigned lob = g_lob;
    const float td = __uint_as_float(g_tbd);
    int t = blockIdx.x * 256 + threadIdx.x;
    float l1loc = 0.f;
    int l0loc = 0;
#pragma unroll 4
    for (int r = 0; r < 120; r++) {
        int i = t + r * NTHR;
        float v = g_acts[i];
        int row = i / S_N;
        int col = i - row * S_N;
        unsigned u = __float_as_uint(v);
        bool pos = v > 0.f;
        bool keep = pos && (u > hib);
        outp[i] = keep ? v : 0.f;
        if (keep) {
            l1loc += v; l0loc++;
            int p = atomicAdd(&g_tcnt[row], 1);
            if (p < TOPCAP) {
                g_tcol[row * TOPCAP + p] = (unsigned short)col;
                g_tval[row * TOPCAP + p] = v;
            }
        }
        wappend((unsigned*)g_bidx, &g_nband, BANDCAP,
                pos && !keep && (u > lob), (unsigned)i);
        if (g_dead[col]) {
            float d = v - td;
            if (d > 0.f) {
                int p = atomicAdd(&g_acnt[row], 1);
                if (p < AUXCAP) {
                    g_acol[(size_t)row * AUXCAP + p] = (unsigned short)col;
                    g_aval[(size_t)row * AUXCAP + p] = d;
                }
            }
        }
    }
    redf[threadIdx.x] = l1loc;
    redi[threadIdx.x] = l0loc;
    __syncthreads();
    for (int s = 128; s > 0; s >>= 1) {
        if (threadIdx.x < s) {
            redf[threadIdx.x] += redf[threadIdx.x + s];
            redi[threadIdx.x] += redi[threadIdx.x + s];
        }
        __syncthreads();
    }
    if (threadIdx.x == 0) {
        atomicAdd(&g_l1s, (double)redf[0]);
        atomicAdd(&g_l0s, (unsigned long long)redi[0]);
        atomicAdd(&g_nhi, redi[0]);
    }
}

/* ------------------------- exact dot (double-f32, coalesced WTe) -------- */
__device__ __forceinline__ void exact_dot(int row, int col, int lane,
                                          float& sh_out, float& sl_out) {
    const float* xr = &g_xc[row * D_N];
    const float* wr = &g_WTe[(size_t)col * D_N];
    float sh = 0.f, sl = 0.f;
#pragma unroll 4
    for (int j = 0; j < 32; j++) {
        int k = lane + j * 32;
        float a = xr[k], b = wr[k];
        float ph = fmul_rn(a, b);
        float pl = ffma_rn(a, b, -ph);
        float s  = fadd_rn(sh, ph);
        float bb = fsub_rn(s, sh);
        float e1 = fsub_rn(sh, fsub_rn(s, bb));
        float e2 = fsub_rn(ph, bb);
        sh = s;
        sl = fadd_rn(sl, fadd_rn(fadd_rn(e1, e2), pl));
    }
    for (int off = 16; off; off >>= 1) {
        float oh = __shfl_down_sync(0xffffffffu, sh, off);
        float ol = __shfl_down_sync(0xffffffffu, sl, off);
        float s  = fadd_rn(sh, oh);
        float bb = fsub_rn(s, sh);
        float e1 = fsub_rn(sh, fsub_rn(s, bb));
        float e2 = fsub_rn(oh, bb);
        sh = s;
        sl = fadd_rn(sl, fadd_rn(fadd_rn(e1, e2), ol));
    }
    sh_out = sh; sl_out = sl;
}

/* exact band dots */
__global__ void band_dot_kernel(const float* __restrict__ b_enc) {
    int w = (blockIdx.x * 256 + threadIdx.x) >> 5;
    int lane = threadIdx.x & 31;
    int nb = min(g_nband, (int)BANDCAP);
    if (w >= nb) return;
    int idx = g_bidx[w];
    int row = idx / S_N, col = idx - row * S_N;
    float sh, sl;
    exact_dot(row, col, lane, sh, sl);
    if (lane == 0) {
        double val = (double)sh + (double)sl + (double)b_enc[col];
        float hh = (float)val;
        g_bhi[w] = hh;
        g_blo[w] = (float)(val - (double)hh);
    }
}

/* ------------------------- band ranking + commit (adaptive bitonic) ----- */
__global__ __launch_bounds__(1024) void band_rank_kernel(float* __restrict__ outp) {
    extern __shared__ char bsm[];
    double* sval = (double*)bsm;
    int*    sidx = (int*)(bsm + (size_t)BANDCAP * 8);
    __shared__ double rsm[32];
    int tid = threadIdx.x;
    int nb = min(g_nband, (int)BANDCAP);
    int nb2 = 2048;
    while (nb2 < nb) nb2 <<= 1;          /* adaptive sort size (pow2 >= nb) */
    for (int i = tid; i < nb2; i += 1024) {
        if (i < nb) {
            sval[i] = (double)g_bhi[i] + (double)g_blo[i];
            sidx[i] = g_bidx[i];
        } else {
            sval[i] = -1e300;
            sidx[i] = 0x7fffffff;
        }
    }
    __syncthreads();
    for (int size = 2; size <= nb2; size <<= 1) {
        for (int stride = size >> 1; stride; stride >>= 1) {
            for (int i = tid; i < nb2 / 2; i += 1024) {
                int pos = 2 * i - (i & (stride - 1));
                int a = pos, b = pos + stride;
                bool dirDesc = ((pos & size) == 0);
                bool agtb = (sval[a] != sval[b]) ? (sval[a] > sval[b])
                                                 : (sidx[a] < sidx[b]);
                if (dirDesc ? !agtb : agtb) {
                    double tv = sval[a]; sval[a] = sval[b]; sval[b] = tv;
                    int ti = sidx[a]; sidx[a] = sidx[b]; sidx[b] = ti;
                }
            }
            __syncthreads();
        }
    }
    int needK = (int)KTOP - g_nhi;
    if (needK < 0) needK = 0;
    if (needK > nb) needK = nb;
    double l1loc = 0.0;
    for (int i = tid; i < needK; i += 1024) {
        int idx = sidx[i];
        float fv = (float)sval[i];
        outp[idx] = fv;
        int row = idx / S_N, col = idx - row * S_N;
        int p = atomicAdd(&g_tcnt[row], 1);
        if (p < TOPCAP) {
            g_tcol[row * TOPCAP + p] = (unsigned short)col;
            g_tval[row * TOPCAP + p] = fv;
        }
        l1loc += (double)fv;
    }
    for (int off = 16; off; off >>= 1)
        l1loc += __shfl_down_sync(0xffffffffu, l1loc, off);
    if ((tid & 31) == 0) rsm[tid >> 5] = l1loc;
    __syncthreads();
    if (tid == 0) {
        double s = 0.0;
        for (int q = 0; q < 32; q++) s += rsm[q];
        atomicAdd(&g_l1s, s);
        atomicAdd(&g_l0s, (unsigned long long)needK);
    }
}

/* ------------------------- sparse Matryoshka decode ------------------------- */
__global__ void decode_kernel(const float* __restrict__ x,
                              const float* __restrict__ b_dec,
                              const float* __restrict__ W_dec,
                              float* __restrict__ out_recon)
{
    __shared__ unsigned short scol[TOPCAP];
    __shared__ float sval[TOPCAP];
    __shared__ float red[256];
    int row = blockIdx.x, tid = threadIdx.x;
    int cnt = min(g_tcnt[row], TOPCAP);
    for (int i = tid; i < cnt; i += 256) {
        scol[i] = g_tcol[row * TOPCAP + i];
        sval[i] = g_tval[row * TOPCAP + i];
    }
    __syncthreads();
    int d = tid * 4;
    float4 acc = *(const float4*)&b_dec[d];
    float4 xv = *(const float4*)&x[row * D_N + d];
    const int bounds[5] = {0, 2048, 6144, 14336, 30720};
#pragma unroll
    for (int g = 0; g < 4; g++) {
        int lo = bounds[g], hi = bounds[g + 1];
        for (int e = 0; e < cnt; e++) {
            int c = scol[e];
            if (c >= lo && c < hi) {
                float vv = sval[e];
                float4 w = *(const float4*)&W_dec[(size_t)c * D_N + d];
                acc.x += vv * w.x; acc.y += vv * w.y;
                acc.z += vv * w.z; acc.w += vv * w.w;
            }
        }
        float dx = acc.x - xv.x, dy = acc.y - xv.y;
        float dz = acc.z - xv.z, dw = acc.w - xv.w;
        red[tid] = dx * dx + dy * dy + dz * dz + dw * dw;
        __syncthreads();
        for (int s = 128; s > 0; s >>= 1) {
            if (tid < s) red[tid] += red[tid + s];
            __syncthreads();
        }
        if (tid == 0) atomicAdd(&g_l2s[g], (double)red[0]);
        __syncthreads();
    }
    float* ro = out_recon + (size_t)row * D_N + d;
    ro[0] = acc.x; ro[1] = acc.y; ro[2] = acc.z; ro[3] = acc.w;
    *(float4*)&g_recon[row * D_N + d] = acc;
}

/* ------------------------- aux dense GEMM (smem + ldmatrix + mma.sync) ------- */
#define KCH 32
#define SSTR 40
__global__ __launch_bounds__(256) void aux_gemm(const float* __restrict__ x)
{
    __shared__ __align__(16) __nv_bfloat16 sA[2][128][SSTR];
    __shared__ __align__(16) __nv_bfloat16 sB[2][128][SSTR];
    __shared__ float wsum[8];

    if (g_ndead == 0) return;
    const int pad = g_ndead_pad;
    const int nchunks = pad / KCH;
    const int tid = threadIdx.x;
    const int wid = tid >> 5;
    const int lane = tid & 31;
    const int warp_m = wid & 3;
    const int warp_n = wid >> 2;
    const int bm = blockIdx.x * 128;
    const int bn = blockIdx.y * 128;
    const int m0 = bm + warp_m * 32;
    const int n0l = warp_n * 64;

    float acc[2][8][4];
#pragma unroll
    for (int mt = 0; mt < 2; mt++)
#pragma unroll
        for (int nt = 0; nt < 8; nt++)
#pragma unroll
            for (int q = 0; q < 4; q++) acc[mt][nt][q] = 0.f;

    const int lrow = tid >> 1;
    const int lseg = tid & 1;

#define LOAD_CHUNK(c, b)                                                        \
    do {                                                                        \
        int kof = (c) * KCH;                                                    \
        cp16(smem_u32(&sA[b][lrow][(lseg) * 8]),                                \
             &g_A[(size_t)(bm + lrow) * pad + kof + (lseg) * 8]);               \
        cp16(smem_u32(&sA[b][lrow][(lseg + 2) * 8]),                            \
             &g_A[(size_t)(bm + lrow) * pad + kof + (lseg + 2) * 8]);           \
        cp16(smem_u32(&sB[b][lrow][(lseg) * 8]),                                \
             &g_WT[(size_t)(bn + lrow) * pad + kof + (lseg) * 8]);              \
        cp16(smem_u32(&sB[b][lrow][(lseg + 2) * 8]),                            \
             &g_WT[(size_t)(bn + lrow) * pad + kof + (lseg + 2) * 8]);          \
        asm volatile("cp.async.commit_group;" ::: "memory");                    \
    } while (0)

    LOAD_CHUNK(0, 0);

    const int lr = (lane & 7) + (lane & 8);
    const int lc = (lane >> 4) << 3;

    for (int c = 0; c < nchunks; c++) {
        int buf = c & 1;
        if (c + 1 < nchunks) {
            LOAD_CHUNK(c + 1, (c + 1) & 1);
            asm volatile("cp.async.wait_group 1;" ::: "memory");
        } else {
            asm volatile("cp.async.wait_group 0;" ::: "memory");
        }
        __syncthreads();

#pragma unroll
        for (int ks = 0; ks < KCH / 16; ks++) {
            int k0 = ks * 16;
            unsigned a[2][4];
#pragma unroll
            for (int mt = 0; mt < 2; mt++) {
                unsigned addr = smem_u32(&sA[buf][warp_m * 32 + mt * 16 + lr][k0 + lc]);
                ldm4(a[mt][0], a[mt][1], a[mt][2], a[mt][3], addr);
            }
            unsigned bb[8][2];
#pragma unroll
            for (int p = 0; p < 4; p++) {
                unsigned r0, r1, r2, r3;
                unsigned addr = smem_u32(&sB[buf][n0l + p * 16 + lr][k0 + lc]);
                ldm4(r0, r1, r2, r3, addr);
                bb[2 * p][0] = r0; bb[2 * p + 1][0] = r1;
                bb[2 * p][1] = r2; bb[2 * p + 1][1] = r3;
            }
#pragma unroll
            for (int mt = 0; mt < 2; mt++)
#pragma unroll
                for (int nt = 0; nt < 8; nt++)
                    mma_bf16(acc[mt][nt], a[mt], bb[nt]);
        }
        __syncthreads();
    }

    const int crow = lane >> 2;
    const int ccol = (lane & 3) * 2;
    const int n0 = bn + n0l;
    float sum = 0.f;
#pragma unroll
    for (int mt = 0; mt < 2; mt++) {
#pragma unroll
        for (int nt = 0; nt < 8; nt++) {
            int m1 = m0 + mt * 16 + crow;
            int m2 = m1 + 8;
            int dd = n0 + nt * 8 + ccol;
            float2 xv1 = *(const float2*)&x[(size_t)m1 * D_N + dd];
            float2 rv1 = *(const float2*)&g_recon[(size_t)m1 * D_N + dd];
            float2 xv2 = *(const float2*)&x[(size_t)m2 * D_N + dd];
            float2 rv2 = *(const float2*)&g_recon[(size_t)m2 * D_N + dd];
            float d0 = acc[mt][nt][0] - (xv1.x - rv1.x);
            float d1 = acc[mt][nt][1] - (xv1.y - rv1.y);
            float d2 = acc[mt][nt][2] - (xv2.x - rv2.x);
            float d3 = acc[mt][nt][3] - (xv2.y - rv2.y);
            sum += d0 * d0 + d1 * d1 + d2 * d2 + d3 * d3;
        }
    }
    for (int off = 16; off; off >>= 1)
        sum += __shfl_down_sync(0xffffffffu, sum, off);
    if (lane == 0) wsum[wid] = sum;
    __syncthreads();
    if (tid == 0) {
        float s = 0.f;
        for (int w = 0; w < 8; w++) s += wsum[w];
        atomicAdd(&g_auxs, (double)s);
    }
}

/* ------------------------- finalize ------------------------- */
__global__ void fin_kernel(float* __restrict__ out) {
    double inv = 1.0 / ((double)B_N * (double)D_N);
    double l2m = (g_l2s[0] + g_l2s[1] + g_l2s[2] + g_l2s[3]) * 0.25 * inv;
    double l1 = 1e-3 * g_l1s / (double)B_N;
    double l0 = (double)g_l0s / (double)B_N;
    double aux = g_any_dead ? (1e-2 * g_auxs * inv) : 0.0;
    out[0] = (float)(l2m + l1 + aux);
    out[1] = (float)l2m;
    out[2] = (float)l1;
    out[3] = (float)aux;
    out[4] = (float)l0;
}

/* ------------------------- launch ------------------------- */
extern "C" void kernel_launch(void* const* d_in, const int* in_sizes, int n_in,
                              void* d_out, int out_size) {
    const float* x     = (const float*)d_in[0];
    const float* b_dec = (const float*)d_in[1];
    const float* b_enc = (const float*)d_in[2];
    const float* W_enc = (const float*)d_in[3];
    const float* W_dec = (const float*)d_in[4];
    const int*   nbna  = (const int*)d_in[5];
    float* out = (float*)d_out;
    float* out_topk  = out + 5;
    float* out_recon = out + 5 + (size_t)B_N * S_N;

    static int attrs_set = 0;
    if (!attrs_set) {
        cudaFuncSetAttribute(enc_mma, cudaFuncAttributeMaxDynamicSharedMemorySize,
                             4 * 128 * ESTR * 2);
        cudaFuncSetAttribute(band_rank_kernel,
                             cudaFuncAttributeMaxDynamicSharedMemorySize,
                             BANDCAP * 12);
        attrs_set = 1;
    }

    reset_kernel<<<(S_N + 255) / 256, 256>>>(nbna);
    dm1_kernel<<<30, 1024>>>();
    dm2_kernel<<<1, 1>>>();
    dm3_kernel<<<30, 1024>>>();
    zeroA_kernel<<<2048, 256>>>();
    wtT_kernel<<<dim3(S_N / 64, D_N / 64), 256>>>(W_dec);
    sub_kernel<<<B_N * D_N / 4 / 256, 256>>>(x, b_dec);
    whl_kernel<<<dim3(S_N / 64, D_N / 64), 256>>>(W_enc);
    enc_mma<<<dim3(B_N / 128, S_N / 128), 512, 4 * 128 * ESTR * 2>>>(b_enc);
    hist1_kernel<<<2048, 256>>>();
    scan1_kernel<<<1, 256>>>();
    l2hist_kernel<<<2048, 256>>>();
    scan2_kernel<<<1, 1>>>();
    scatter_kernel<<<2048, 256>>>(out_topk);
    band_dot_kernel<<<BANDCAP / 8, 256>>>(b_enc);
    band_rank_kernel<<<1, 1024, BANDCAP * 12>>>(out_topk);
    Ascatter_kernel<<<B_N, 256>>>();
    decode_kernel<<<B_N, 256>>>(x, b_dec, W_dec, out_recon);
    aux_gemm<<<dim3(B_N / 128, D_N / 128), 256>>>(x);
    fin_kernel<<<1, 1>>>(out);
}

// round 16
// speedup vs baseline: 1.4897x; 1.0525x over previous
#include <cuda_runtime.h>
#include <cuda_bf16.h>
#include <cuda_fp16.h>
#include <cstdint>

#define B_N   2048
#define D_N   1024
#define S_N   30720
#define SN4   7680
#define NTHR  524288
#define KTOP  131072u
#define KAUX  2097152u
#define TOPCAP 160
#define AUXCAP 2048
#define BANDCAP 16384

/* ------------------------- scratch ------------------------- */
__device__ float g_acts[(size_t)B_N * S_N];
__device__ float g_xc[B_N * D_N];
__device__ float g_recon[B_N * D_N];
__device__ float g_D[B_N * D_N];                     /* aux GEMM result */
__device__ unsigned g_hist_a[4096];
__device__ unsigned g_hist_d[4096];
__device__ unsigned char g_dead[S_N];
__device__ int g_any_dead;
__device__ int g_b1a, g_b1d, g_b2a, g_b2d;
__device__ unsigned g_r1a, g_r1d;
__device__ unsigned g_tba, g_tbd;
__device__ unsigned g_hib, g_lob;
__device__ int g_bidx[BANDCAP];
__device__ float g_bhi[BANDCAP], g_blo[BANDCAP];
__device__ int g_nband, g_nhi;
__device__ unsigned short g_tcol[B_N * TOPCAP];
__device__ float          g_tval[B_N * TOPCAP];
__device__ int            g_tcnt[B_N];
__device__ unsigned short g_acol[(size_t)B_N * AUXCAP];
__device__ float          g_aval[(size_t)B_N * AUXCAP];
__device__ int            g_acnt[B_N];
__device__ double g_l2s[4];
__device__ double g_l1s;
__device__ unsigned long long g_l0s;
__device__ double g_auxs;

/* encoder fp16 GEMM scratch */
__device__ __half g_xhi[B_N * D_N];
__device__ __half g_Whi[(size_t)S_N * D_N];
__device__ float  g_WTe[(size_t)S_N * D_N];

/* dense aux GEMM scratch */
__device__ __nv_bfloat16 g_A[(size_t)B_N * S_N];
__device__ __nv_bfloat16 g_WT[(size_t)D_N * S_N];
__device__ int g_dmap[S_N];
__device__ int g_dinv[S_N];
__device__ int g_dcnt[32];
__device__ int g_ndead, g_ndead_pad;

/* ------------------------- exact f32 helpers ------------------------- */
__device__ __forceinline__ float fadd_rn(float a, float b) {
    float r; asm("add.rn.f32 %0, %1, %2;" : "=f"(r) : "f"(a), "f"(b)); return r;
}
__device__ __forceinline__ float fsub_rn(float a, float b) {
    float r; asm("sub.rn.f32 %0, %1, %2;" : "=f"(r) : "f"(a), "f"(b)); return r;
}
__device__ __forceinline__ float fmul_rn(float a, float b) {
    float r; asm("mul.rn.f32 %0, %1, %2;" : "=f"(r) : "f"(a), "f"(b)); return r;
}
__device__ __forceinline__ float ffma_rn(float a, float b, float c) {
    float r; asm("fma.rn.f32 %0, %1, %2, %3;" : "=f"(r) : "f"(a), "f"(b), "f"(c)); return r;
}

/* mma.sync bf16 / fp16 (baseline PTX, plain sm_103) */
__device__ __forceinline__ void mma_bf16(float* c, const unsigned* a, const unsigned* b) {
    asm volatile(
        "mma.sync.aligned.m16n8k16.row.col.f32.bf16.bf16.f32 "
        "{%0,%1,%2,%3}, {%4,%5,%6,%7}, {%8,%9}, {%0,%1,%2,%3};"
        : "+f"(c[0]), "+f"(c[1]), "+f"(c[2]), "+f"(c[3])
        : "r"(a[0]), "r"(a[1]), "r"(a[2]), "r"(a[3]), "r"(b[0]), "r"(b[1]));
}
__device__ __forceinline__ void mma_fp16(float* c, const unsigned* a, const unsigned* b) {
    asm volatile(
        "mma.sync.aligned.m16n8k16.row.col.f32.f16.f16.f32 "
        "{%0,%1,%2,%3}, {%4,%5,%6,%7}, {%8,%9}, {%0,%1,%2,%3};"
        : "+f"(c[0]), "+f"(c[1]), "+f"(c[2]), "+f"(c[3])
        : "r"(a[0]), "r"(a[1]), "r"(a[2]), "r"(a[3]), "r"(b[0]), "r"(b[1]));
}
__device__ __forceinline__ uint32_t smem_u32(const void* p) {
    uint32_t a;
    asm("{ .reg .u64 t; cvta.to.shared.u64 t, %1; cvt.u32.u64 %0, t; }"
        : "=r"(a) : "l"(p));
    return a;
}
__device__ __forceinline__ void ldm4(unsigned &r0, unsigned &r1,
                                     unsigned &r2, unsigned &r3, unsigned addr) {
    asm volatile("ldmatrix.sync.aligned.m8n8.x4.shared.b16 {%0,%1,%2,%3}, [%4];"
                 : "=r"(r0), "=r"(r1), "=r"(r2), "=r"(r3) : "r"(addr));
}
__device__ __forceinline__ void cp16(unsigned saddr, const void* gptr) {
    asm volatile("cp.async.cg.shared.global [%0], [%1], 16;"
                 :: "r"(saddr), "l"(gptr) : "memory");
}

/* ------------------------- setup ------------------------- */
__global__ void reset_kernel(const int* __restrict__ nbna) {
    int i = blockIdx.x * 256 + threadIdx.x;
    if (i == 0) {
        g_nband = 0; g_nhi = 0;
        g_l1s = 0.0; g_l0s = 0ull; g_auxs = 0.0; g_any_dead = 0;
        g_l2s[0] = g_l2s[1] = g_l2s[2] = g_l2s[3] = 0.0;
    }
    if (i < 4096) { g_hist_a[i] = 0; g_hist_d[i] = 0; }
    if (i < B_N) { g_tcnt[i] = 0; g_acnt[i] = 0; }
    if (i < S_N) {
        unsigned char d = (nbna[i] >= 20) ? 1 : 0;
        g_dead[i] = d;
        if (d) g_any_dead = 1;
    }
}

/* dead-feature dense mapping */
__global__ void dm1_kernel() {
    __shared__ int red[1024];
    int i = blockIdx.x * 1024 + threadIdx.x;
    red[threadIdx.x] = g_dead[i] ? 1 : 0;
    __syncthreads();
    for (int s = 512; s > 0; s >>= 1) {
        if (threadIdx.x < s) red[threadIdx.x] += red[threadIdx.x + s];
        __syncthreads();
    }
    if (threadIdx.x == 0) g_dcnt[blockIdx.x] = red[0];
}
__global__ void dm2_kernel() {
    int run = 0;
    for (int b = 0; b < 30; b++) {
        int c = g_dcnt[b];
        g_dcnt[b] = run;
        run += c;
    }
    g_ndead = run;
    g_ndead_pad = (run + 63) & ~63;
}
__global__ void dm3_kernel() {
    __shared__ int sc[1024];
    int i = blockIdx.x * 1024 + threadIdx.x;
    int f = g_dead[i] ? 1 : 0;
    sc[threadIdx.x] = f;
    __syncthreads();
    for (int off = 1; off < 1024; off <<= 1) {
        int v = (threadIdx.x >= off) ? sc[threadIdx.x - off] : 0;
        __syncthreads();
        sc[threadIdx.x] += v;
        __syncthreads();
    }
    if (f) {
        int dense = g_dcnt[blockIdx.x] + sc[threadIdx.x] - 1;
        g_dmap[i] = dense;
        g_dinv[dense] = i;
    }
}

__global__ void zeroA_kernel() {
    size_t tot = (size_t)B_N * (size_t)g_ndead_pad / 4;
    uint2 z = {0u, 0u};
    uint2* p = (uint2*)g_A;
    size_t stride = (size_t)gridDim.x * blockDim.x;
    for (size_t i = blockIdx.x * (size_t)blockDim.x + threadIdx.x; i < tot; i += stride)
        p[i] = z;
}

/* W_dec^T (dead cols) bf16 tiled transpose */
__global__ void wtT_kernel(const float* __restrict__ W_dec) {
    __shared__ float tile[64][65];
    int pad = g_ndead_pad;
    int nd  = g_ndead;
    int j0 = blockIdx.x * 64;
    if (j0 >= pad) return;
    int d0 = blockIdx.y * 64;
    int t = threadIdx.x;
#pragma unroll
    for (int s = 0; s < 16; s++) {
        int idx = t + s * 256;
        int jl = idx >> 6, dl = idx & 63;
        int j = j0 + jl;
        float v = 0.f;
        if (j < nd) v = W_dec[(size_t)g_dinv[j] * D_N + d0 + dl];
        tile[jl][dl] = v;
    }
    __syncthreads();
#pragma unroll
    for (int s = 0; s < 16; s++) {
        int idx = t + s * 256;
        int dl = idx >> 6, jl = idx & 63;
        g_WT[(size_t)(d0 + dl) * pad + j0 + jl] = __float2bfloat16(tile[jl][dl]);
    }
}

/* W_enc transpose: [k][n] f32 -> [n][k] f32 exact + fp16 */
__global__ void whl_kernel(const float* __restrict__ W) {
    __shared__ float tile[64][65];
    int n0 = blockIdx.x * 64;
    int k0 = blockIdx.y * 64;
    int t = threadIdx.x;
#pragma unroll
    for (int s = 0; s < 16; s++) {
        int idx = t + s * 256;
        int kl = idx >> 6, nl = idx & 63;
        tile[kl][nl] = W[(size_t)(k0 + kl) * S_N + n0 + nl];
    }
    __syncthreads();
#pragma unroll
    for (int s = 0; s < 16; s++) {
        int idx = t + s * 256;
        int nl = idx >> 6, kl = idx & 63;
        float v = tile[kl][nl];
        g_WTe[(size_t)(n0 + nl) * D_N + k0 + kl] = v;
        g_Whi[(size_t)(n0 + nl) * D_N + k0 + kl] = __float2half_rn(v);
    }
}

/* scatter COO aux values into dense bf16 A */
__global__ void Ascatter_kernel() {
    int row = blockIdx.x;
    int pad = g_ndead_pad;
    int cnt = min(g_acnt[row], AUXCAP);
    for (int i = threadIdx.x; i < cnt; i += 256) {
        int col = g_acol[(size_t)row * AUXCAP + i];
        float v = g_aval[(size_t)row * AUXCAP + i];
        g_A[(size_t)row * pad + g_dmap[col]] = __float2bfloat16(v);
    }
}

/* xc = x - b_dec  (f32 + fp16) */
__global__ void sub_kernel(const float* __restrict__ x,
                           const float* __restrict__ b_dec) {
    int i = blockIdx.x * 256 + threadIdx.x;
    float4 xv = ((const float4*)x)[i];
    float4 bv = ((const float4*)b_dec)[i & 255];
    float4 o;
    o.x = xv.x - bv.x; o.y = xv.y - bv.y;
    o.z = xv.z - bv.z; o.w = xv.w - bv.w;
    ((float4*)g_xc)[i] = o;
    ((__half2*)g_xhi)[i * 2]     = __floats2half2_rn(o.x, o.y);
    ((__half2*)g_xhi)[i * 2 + 1] = __floats2half2_rn(o.z, o.w);
}

/* ------------- encoder GEMM (fp16 mma.sync) ---------- */
#define EKCH 64
#define ESTR 72
__global__ __launch_bounds__(512) void enc_mma(const float* __restrict__ b_enc)
{
    extern __shared__ __half esm[];
    __half* sA = esm;
    __half* sB = esm + 2 * 128 * ESTR;

    const int tid = threadIdx.x;
    const int wid = tid >> 5, lane = tid & 31;
    const int warp_m = wid & 7;
    const int warp_n = wid >> 3;
    const int bm = blockIdx.x * 128;
    const int bn = blockIdx.y * 128;

    float acc[8][4];
#pragma unroll
    for (int nt = 0; nt < 8; nt++)
#pragma unroll
        for (int q = 0; q < 4; q++) acc[nt][q] = 0.f;

    const int lrow = tid >> 2;
    const int lcol = (tid & 3) * 16;

#define ELOAD(c, b) do {                                                     \
    int kof = (c) * EKCH + lcol;                                             \
    const __half* gA = &g_xhi[(size_t)(bm + lrow) * D_N + kof];              \
    const __half* gB = &g_Whi[(size_t)(bn + lrow) * D_N + kof];              \
    unsigned dA = smem_u32(sA + (b) * 128 * ESTR + lrow * ESTR + lcol);      \
    unsigned dB = smem_u32(sB + (b) * 128 * ESTR + lrow * ESTR + lcol);      \
    cp16(dA, gA); cp16(dA + 16, gA + 8);                                     \
    cp16(dB, gB); cp16(dB + 16, gB + 8);                                     \
    asm volatile("cp.async.commit_group;" ::: "memory");                     \
} while (0)

    ELOAD(0, 0);

    const int lr = (lane & 7) + (lane & 8);
    const int lc = (lane >> 4) << 3;

    for (int c = 0; c < 16; c++) {
        int buf = c & 1;
        if (c < 15) {
            ELOAD(c + 1, buf ^ 1);
            asm volatile("cp.async.wait_group 1;" ::: "memory");
        } else {
            asm volatile("cp.async.wait_group 0;" ::: "memory");
        }
        __syncthreads();
#pragma unroll
        for (int ks = 0; ks < 4; ks++) {
            int k0 = ks * 16;
            unsigned a[4];
            {
                unsigned addr = smem_u32(sA + buf * 128 * ESTR +
                                         (warp_m * 16 + lr) * ESTR + k0 + lc);
                ldm4(a[0], a[1], a[2], a[3], addr);
            }
            unsigned bb[8][2];
#pragma unroll
            for (int p = 0; p < 4; p++) {
                unsigned r0, r1, r2, r3;
                unsigned addr = smem_u32(sB + buf * 128 * ESTR +
                                         (warp_n * 64 + p * 16 + lr) * ESTR + k0 + lc);
                ldm4(r0, r1, r2, r3, addr);
                bb[2 * p][0] = r0; bb[2 * p + 1][0] = r1;
                bb[2 * p][1] = r2; bb[2 * p + 1][1] = r3;
            }
#pragma unroll
            for (int nt = 0; nt < 8; nt++)
                mma_fp16(acc[nt], a, bb[nt]);
        }
        __syncthreads();
    }

    const int crow = lane >> 2, ccol = (lane & 3) * 2;
    const int m1 = bm + warp_m * 16 + crow;
#pragma unroll
    for (int nt = 0; nt < 8; nt++) {
        int n = bn + warp_n * 64 + nt * 8 + ccol;
        float2 be = *(const float2*)&b_enc[n];
        float2 o1, o2;
        o1.x = fmaxf(acc[nt][0] + be.x, 0.f);
        o1.y = fmaxf(acc[nt][1] + be.y, 0.f);
        o2.x = fmaxf(acc[nt][2] + be.x, 0.f);
        o2.y = fmaxf(acc[nt][3] + be.y, 0.f);
        *(float2*)&g_acts[(size_t)m1 * S_N + n] = o1;
        *(float2*)&g_acts[(size_t)(m1 + 8) * S_N + n] = o2;
    }
}

/* ------------------------- level-1 histogram ------------------------- */
__global__ void hist1_kernel() {
    __shared__ unsigned ha[4096];
    __shared__ unsigned hd[4096];
    for (int i = threadIdx.x; i < 4096; i += 256) { ha[i] = 0; hd[i] = 0; }
    __syncthreads();
    int t = blockIdx.x * 256 + threadIdx.x;
    const float4* A4 = (const float4*)g_acts;
    for (int r = 0; r < 30; r++) {
        int i4 = t + r * NTHR;
        float4 v = A4[i4];
        int cb = (i4 % SN4) * 4;
        uchar4 dd = *(const uchar4*)&g_dead[cb];
        float vv[4] = {v.x, v.y, v.z, v.w};
        unsigned char dm[4] = {dd.x, dd.y, dd.z, dd.w};
#pragma unroll
        for (int j = 0; j < 4; j++) {
            if (vv[j] > 0.f) {
                unsigned bin = __float_as_uint(vv[j]) >> 20;
                atomicAdd(&ha[bin], 1u);
                if (dm[j]) atomicAdd(&hd[bin], 1u);
            }
        }
    }
    __syncthreads();
    for (int i = threadIdx.x; i < 4096; i += 256) {
        if (ha[i]) atomicAdd(&g_hist_a[i], ha[i]);
        if (hd[i]) atomicAdd(&g_hist_d[i], hd[i]);
    }
}

__global__ void scan1_kernel() {
    if (threadIdx.x == 0) {
        unsigned long long cum = 0;
        for (int b = 4095; b >= 0; b--) {
            cum += g_hist_a[b];
            if (cum >= (unsigned long long)KTOP) {
                g_b1a = b; g_r1a = KTOP - (unsigned)(cum - g_hist_a[b]); break;
            }
        }
        cum = 0;
        for (int b = 4095; b >= 0; b--) {
            cum += g_hist_d[b];
            if (cum >= (unsigned long long)KAUX) {
                g_b1d = b; g_r1d = KAUX - (unsigned)(cum - g_hist_d[b]); break;
            }
        }
    }
    __syncthreads();
    for (int i = threadIdx.x; i < 4096; i += 256) { g_hist_a[i] = 0; g_hist_d[i] = 0; }
}

/* ------------------- level-2 histogram fused (reads g_acts) ------------- */
__global__ void l2hist_kernel() {
    __shared__ unsigned ha[4096];
    __shared__ unsigned hd[4096];
    for (int i = threadIdx.x; i < 4096; i += 256) { ha[i] = 0; hd[i] = 0; }
    __syncthreads();
    int t = blockIdx.x * 256 + threadIdx.x;
    const unsigned b1a = (unsigned)g_b1a, b1d = (unsigned)g_b1d;
    const float4* A4 = (const float4*)g_acts;
    for (int r = 0; r < 30; r++) {
        int i4 = t + r * NTHR;
        float4 v = A4[i4];
        int cb = (i4 % SN4) * 4;
        uchar4 dd = *(const uchar4*)&g_dead[cb];
        float vv[4] = {v.x, v.y, v.z, v.w};
        unsigned char dm[4] = {dd.x, dd.y, dd.z, dd.w};
#pragma unroll
        for (int j = 0; j < 4; j++) {
            unsigned u = __float_as_uint(vv[j]);
            bool pos = vv[j] > 0.f;
            if (pos && ((u >> 20) == b1a)) atomicAdd(&ha[(u >> 8) & 0xFFF], 1u);
            if (pos && dm[j] && ((u >> 20) == b1d)) atomicAdd(&hd[(u >> 8) & 0xFFF], 1u);
        }
    }
    __syncthreads();
    for (int i = threadIdx.x; i < 4096; i += 256) {
        if (ha[i]) atomicAdd(&g_hist_a[i], ha[i]);
        if (hd[i]) atomicAdd(&g_hist_d[i], hd[i]);
    }
}

__global__ void scan2_kernel() {
    if (threadIdx.x == 0) {
        unsigned long long cum = 0; unsigned K = g_r1a;
        for (int b = 4095; b >= 0; b--) {
            cum += g_hist_a[b];
            if (cum >= (unsigned long long)K) { g_b2a = b; break; }
        }
        cum = 0; K = g_r1d;
        for (int b = 4095; b >= 0; b--) {
            cum += g_hist_d[b];
            if (cum >= (unsigned long long)K) { g_b2d = b; break; }
        }
        g_tba = ((unsigned)g_b1a << 20) | ((unsigned)g_b2a << 8);
        g_tbd = ((unsigned)g_b1d << 20) | ((unsigned)g_b2d << 8);
        float t = __uint_as_float(g_tba);
        g_hib = __float_as_uint(t * (1.0f + 3.2e-3f));
        g_lob = __float_as_uint(t * (1.0f - 3.0e-3f));
    }
}

/* ------------------------- candidate append helper ---------------------- */
__device__ __forceinline__ void wappend(unsigned* buf, int* ctr, unsigned cap,
                                        bool pred, unsigned val) {
    unsigned m = __ballot_sync(0xffffffffu, pred);
    if (!m) return;
    int lane = threadIdx.x & 31;
    int leader = __ffs(m) - 1;
    int base = 0;
    if (lane == leader) base = atomicAdd(ctr, __popc(m));
    base = __shfl_sync(0xffffffffu, base, leader);
    if (pred) {
        int pos = base + __popc(m & ((1u << lane) - 1u));
        if ((unsigned)pos < cap) buf[pos] = val;
    }
}

/* ------------------------- scatter (commit values) ---------------------- */
__global__ void scatter_kernel(float* __restrict__ outp) {
    __shared__ float redf[256];
    __shared__ int redi[256];
    const unsigned hib = g_hib;
    const unsigned lob = g_lob;
    const float td = __uint_as_float(g_tbd);
    int t = blockIdx.x * 256 + threadIdx.x;
    float l1loc = 0.f;
    int l0loc = 0;
#pragma unroll 4
    for (int r = 0; r < 120; r++) {
        int i = t + r * NTHR;
        float v = g_acts[i];
        int row = i / S_N;
        int col = i - row * S_N;
        unsigned u = __float_as_uint(v);
        bool pos = v > 0.f;
        bool keep = pos && (u > hib);
        outp[i] = keep ? v : 0.f;
        if (keep) {
            l1loc += v; l0loc++;
            int p = atomicAdd(&g_tcnt[row], 1);
            if (p < TOPCAP) {
                g_tcol[row * TOPCAP + p] = (unsigned short)col;
                g_tval[row * TOPCAP + p] = v;
            }
        }
        wappend((unsigned*)g_bidx, &g_nband, BANDCAP,
                pos && !keep && (u > lob), (unsigned)i);
        if (g_dead[col]) {
            float d = v - td;
            if (d > 0.f) {
                int p = atomicAdd(&g_acnt[row], 1);
                if (p < AUXCAP) {
                    g_acol[(size_t)row * AUXCAP + p] = (unsigned short)col;
                    g_aval[(size_t)row * AUXCAP + p] = d;
                }
            }
        }
    }
    redf[threadIdx.x] = l1loc;
    redi[threadIdx.x] = l0loc;
    __syncthreads();
    for (int s = 128; s > 0; s >>= 1) {
        if (threadIdx.x < s) {
            redf[threadIdx.x] += redf[threadIdx.x + s];
            redi[threadIdx.x] += redi[threadIdx.x + s];
        }
        __syncthreads();
    }
    if (threadIdx.x == 0) {
        atomicAdd(&g_l1s, (double)redf[0]);
        atomicAdd(&g_l0s, (unsigned long long)redi[0]);
        atomicAdd(&g_nhi, redi[0]);
    }
}

/* ------------------------- exact dot (double-f32, coalesced WTe) -------- */
__device__ __forceinline__ void exact_dot(int row, int col, int lane,
                                          float& sh_out, float& sl_out) {
    const float* xr = &g_xc[row * D_N];
    const float* wr = &g_WTe[(size_t)col * D_N];
    float sh = 0.f, sl = 0.f;
#pragma unroll 4
    for (int j = 0; j < 32; j++) {
        int k = lane + j * 32;
        float a = xr[k], b = wr[k];
        float ph = fmul_rn(a, b);
        float pl = ffma_rn(a, b, -ph);
        float s  = fadd_rn(sh, ph);
        float bb = fsub_rn(s, sh);
        float e1 = fsub_rn(sh, fsub_rn(s, bb));
        float e2 = fsub_rn(ph, bb);
        sh = s;
        sl = fadd_rn(sl, fadd_rn(fadd_rn(e1, e2), pl));
    }
    for (int off = 16; off; off >>= 1) {
        float oh = __shfl_down_sync(0xffffffffu, sh, off);
        float ol = __shfl_down_sync(0xffffffffu, sl, off);
        float s  = fadd_rn(sh, oh);
        float bb = fsub_rn(s, sh);
        float e1 = fsub_rn(sh, fsub_rn(s, bb));
        float e2 = fsub_rn(oh, bb);
        sh = s;
        sl = fadd_rn(sl, fadd_rn(fadd_rn(e1, e2), ol));
    }
    sh_out = sh; sl_out = sl;
}

/* exact band dots */
__global__ void band_dot_kernel(const float* __restrict__ b_enc) {
    int w = (blockIdx.x * 256 + threadIdx.x) >> 5;
    int lane = threadIdx.x & 31;
    int nb = min(g_nband, (int)BANDCAP);
    if (w >= nb) return;
    int idx = g_bidx[w];
    int row = idx / S_N, col = idx - row * S_N;
    float sh, sl;
    exact_dot(row, col, lane, sh, sl);
    if (lane == 0) {
        double val = (double)sh + (double)sl + (double)b_enc[col];
        float hh = (float)val;
        g_bhi[w] = hh;
        g_blo[w] = (float)(val - (double)hh);
    }
}

/* ------------------------- band ranking + commit (adaptive bitonic) ----- */
__global__ __launch_bounds__(1024) void band_rank_kernel(float* __restrict__ outp) {
    extern __shared__ char bsm[];
    double* sval = (double*)bsm;
    int*    sidx = (int*)(bsm + (size_t)BANDCAP * 8);
    __shared__ double rsm[32];
    int tid = threadIdx.x;
    int nb = min(g_nband, (int)BANDCAP);
    int nb2 = 2048;
    while (nb2 < nb) nb2 <<= 1;
    for (int i = tid; i < nb2; i += 1024) {
        if (i < nb) {
            sval[i] = (double)g_bhi[i] + (double)g_blo[i];
            sidx[i] = g_bidx[i];
        } else {
            sval[i] = -1e300;
            sidx[i] = 0x7fffffff;
        }
    }
    __syncthreads();
    for (int size = 2; size <= nb2; size <<= 1) {
        for (int stride = size >> 1; stride; stride >>= 1) {
            for (int i = tid; i < nb2 / 2; i += 1024) {
                int pos = 2 * i - (i & (stride - 1));
                int a = pos, b = pos + stride;
                bool dirDesc = ((pos & size) == 0);
                bool agtb = (sval[a] != sval[b]) ? (sval[a] > sval[b])
                                                 : (sidx[a] < sidx[b]);
                if (dirDesc ? !agtb : agtb) {
                    double tv = sval[a]; sval[a] = sval[b]; sval[b] = tv;
                    int ti = sidx[a]; sidx[a] = sidx[b]; sidx[b] = ti;
                }
            }
            __syncthreads();
        }
    }
    int needK = (int)KTOP - g_nhi;
    if (needK < 0) needK = 0;
    if (needK > nb) needK = nb;
    double l1loc = 0.0;
    for (int i = tid; i < needK; i += 1024) {
        int idx = sidx[i];
        float fv = (float)sval[i];
        outp[idx] = fv;
        int row = idx / S_N, col = idx - row * S_N;
        int p = atomicAdd(&g_tcnt[row], 1);
        if (p < TOPCAP) {
            g_tcol[row * TOPCAP + p] = (unsigned short)col;
            g_tval[row * TOPCAP + p] = fv;
        }
        l1loc += (double)fv;
    }
    for (int off = 16; off; off >>= 1)
        l1loc += __shfl_down_sync(0xffffffffu, l1loc, off);
    if ((tid & 31) == 0) rsm[tid >> 5] = l1loc;
    __syncthreads();
    if (tid == 0) {
        double s = 0.0;
        for (int q = 0; q < 32; q++) s += rsm[q];
        atomicAdd(&g_l1s, s);
        atomicAdd(&g_l0s, (unsigned long long)needK);
    }
}

/* ------------------------- sparse Matryoshka decode ------------------------- */
__global__ void decode_kernel(const float* __restrict__ x,
                              const float* __restrict__ b_dec,
                              const float* __restrict__ W_dec,
                              float* __restrict__ out_recon)
{
    __shared__ unsigned short scol[TOPCAP];
    __shared__ float sval[TOPCAP];
    __shared__ float red[256];
    int row = blockIdx.x, tid = threadIdx.x;
    int cnt = min(g_tcnt[row], TOPCAP);
    for (int i = tid; i < cnt; i += 256) {
        scol[i] = g_tcol[row * TOPCAP + i];
        sval[i] = g_tval[row * TOPCAP + i];
    }
    __syncthreads();
    int d = tid * 4;
    float4 acc = *(const float4*)&b_dec[d];
    float4 xv = *(const float4*)&x[row * D_N + d];
    const int bounds[5] = {0, 2048, 6144, 14336, 30720};
#pragma unroll
    for (int g = 0; g < 4; g++) {
        int lo = bounds[g], hi = bounds[g + 1];
        for (int e = 0; e < cnt; e++) {
            int c = scol[e];
            if (c >= lo && c < hi) {
                float vv = sval[e];
                float4 w = *(const float4*)&W_dec[(size_t)c * D_N + d];
                acc.x += vv * w.x; acc.y += vv * w.y;
                acc.z += vv * w.z; acc.w += vv * w.w;
            }
        }
        float dx = acc.x - xv.x, dy = acc.y - xv.y;
        float dz = acc.z - xv.z, dw = acc.w - xv.w;
        red[tid] = dx * dx + dy * dy + dz * dz + dw * dw;
        __syncthreads();
        for (int s = 128; s > 0; s >>= 1) {
            if (tid < s) red[tid] += red[tid + s];
            __syncthreads();
        }
        if (tid == 0) atomicAdd(&g_l2s[g], (double)red[0]);
        __syncthreads();
    }
    float* ro = out_recon + (size_t)row * D_N + d;
    ro[0] = acc.x; ro[1] = acc.y; ro[2] = acc.z; ro[3] = acc.w;
    *(float4*)&g_recon[row * D_N + d] = acc;
}

/* ----------------- aux dense GEMM mainloop (stores D) ------------------- */
#define KCH 32
#define SSTR 40
__global__ __launch_bounds__(256) void aux_main()
{
    __shared__ __align__(16) __nv_bfloat16 sA[2][128][SSTR];
    __shared__ __align__(16) __nv_bfloat16 sB[2][128][SSTR];

    if (g_ndead == 0) return;
    const int pad = g_ndead_pad;
    const int nchunks = pad / KCH;
    const int tid = threadIdx.x;
    const int wid = tid >> 5;
    const int lane = tid & 31;
    const int warp_m = wid & 3;
    const int warp_n = wid >> 2;
    const int bm = blockIdx.x * 128;
    const int bn = blockIdx.y * 128;
    const int m0 = bm + warp_m * 32;
    const int n0l = warp_n * 64;

    float acc[2][8][4];
#pragma unroll
    for (int mt = 0; mt < 2; mt++)
#pragma unroll
        for (int nt = 0; nt < 8; nt++)
#pragma unroll
            for (int q = 0; q < 4; q++) acc[mt][nt][q] = 0.f;

    const int lrow = tid >> 1;
    const int lseg = tid & 1;

#define LOAD_CHUNK(c, b)                                                        \
    do {                                                                        \
        int kof = (c) * KCH;                                                    \
        cp16(smem_u32(&sA[b][lrow][(lseg) * 8]),                                \
             &g_A[(size_t)(bm + lrow) * pad + kof + (lseg) * 8]);               \
        cp16(smem_u32(&sA[b][lrow][(lseg + 2) * 8]),                            \
             &g_A[(size_t)(bm + lrow) * pad + kof + (lseg + 2) * 8]);           \
        cp16(smem_u32(&sB[b][lrow][(lseg) * 8]),                                \
             &g_WT[(size_t)(bn + lrow) * pad + kof + (lseg) * 8]);              \
        cp16(smem_u32(&sB[b][lrow][(lseg + 2) * 8]),                            \
             &g_WT[(size_t)(bn + lrow) * pad + kof + (lseg + 2) * 8]);          \
        asm volatile("cp.async.commit_group;" ::: "memory");                    \
    } while (0)

    LOAD_CHUNK(0, 0);

    const int lr = (lane & 7) + (lane & 8);
    const int lc = (lane >> 4) << 3;

    for (int c = 0; c < nchunks; c++) {
        int buf = c & 1;
        if (c + 1 < nchunks) {
            LOAD_CHUNK(c + 1, (c + 1) & 1);
            asm volatile("cp.async.wait_group 1;" ::: "memory");
        } else {
            asm volatile("cp.async.wait_group 0;" ::: "memory");
        }
        __syncthreads();

#pragma unroll
        for (int ks = 0; ks < KCH / 16; ks++) {
            int k0 = ks * 16;
            unsigned a[2][4];
#pragma unroll
            for (int mt = 0; mt < 2; mt++) {
                unsigned addr = smem_u32(&sA[buf][warp_m * 32 + mt * 16 + lr][k0 + lc]);
                ldm4(a[mt][0], a[mt][1], a[mt][2], a[mt][3], addr);
            }
            unsigned bb[8][2];
#pragma unroll
            for (int p = 0; p < 4; p++) {
                unsigned r0, r1, r2, r3;
                unsigned addr = smem_u32(&sB[buf][n0l + p * 16 + lr][k0 + lc]);
                ldm4(r0, r1, r2, r3, addr);
                bb[2 * p][0] = r0; bb[2 * p + 1][0] = r1;
                bb[2 * p][1] = r2; bb[2 * p + 1][1] = r3;
            }
#pragma unroll
            for (int mt = 0; mt < 2; mt++)
#pragma unroll
                for (int nt = 0; nt < 8; nt++)
                    mma_bf16(acc[mt][nt], a[mt], bb[nt]);
        }
        __syncthreads();
    }

    /* store D tile (g_D is aligned -> float2 OK) */
    const int crow = lane >> 2;
    const int ccol = (lane & 3) * 2;
    const int n0 = bn + n0l;
#pragma unroll
    for (int mt = 0; mt < 2; mt++) {
#pragma unroll
        for (int nt = 0; nt < 8; nt++) {
            int m1 = m0 + mt * 16 + crow;
            int m2 = m1 + 8;
            int dd = n0 + nt * 8 + ccol;
            float2 v1 = {acc[mt][nt][0], acc[mt][nt][1]};
            float2 v2 = {acc[mt][nt][2], acc[mt][nt][3]};
            *(float2*)&g_D[(size_t)m1 * D_N + dd] = v1;
            *(float2*)&g_D[(size_t)m2 * D_N + dd] = v2;
        }
    }
}

/* ----------------- aux loss epilogue (needs recon) ----------------------- */
__global__ void aux_epi(const float* __restrict__ x) {
    __shared__ float red[256];
    if (g_ndead == 0) return;
    int i = blockIdx.x * 256 + threadIdx.x;
    float4 dv = ((const float4*)g_D)[i];
    float4 xv = ((const float4*)x)[i];
    float4 rv = ((const float4*)g_recon)[i];
    float d0 = dv.x - (xv.x - rv.x);
    float d1 = dv.y - (xv.y - rv.y);
    float d2 = dv.z - (xv.z - rv.z);
    float d3 = dv.w - (xv.w - rv.w);
    red[threadIdx.x] = d0 * d0 + d1 * d1 + d2 * d2 + d3 * d3;
    __syncthreads();
    for (int s = 128; s > 0; s >>= 1) {
        if (threadIdx.x < s) red[threadIdx.x] += red[threadIdx.x + s];
        __syncthreads();
    }
    if (threadIdx.x == 0) atomicAdd(&g_auxs, (double)red[0]);
}

/* ------------------------- finalize ------------------------- */
__global__ void fin_kernel(float* __restrict__ out) {
    double inv = 1.0 / ((double)B_N * (double)D_N);
    double l2m = (g_l2s[0] + g_l2s[1] + g_l2s[2] + g_l2s[3]) * 0.25 * inv;
    double l1 = 1e-3 * g_l1s / (double)B_N;
    double l0 = (double)g_l0s / (double)B_N;
    double aux = g_any_dead ? (1e-2 * g_auxs * inv) : 0.0;
    out[0] = (float)(l2m + l1 + aux);
    out[1] = (float)l2m;
    out[2] = (float)l1;
    out[3] = (float)aux;
    out[4] = (float)l0;
}

/* ------------------------- launch ------------------------- */
extern "C" void kernel_launch(void* const* d_in, const int* in_sizes, int n_in,
                              void* d_out, int out_size) {
    const float* x     = (const float*)d_in[0];
    const float* b_dec = (const float*)d_in[1];
    const float* b_enc = (const float*)d_in[2];
    const float* W_enc = (const float*)d_in[3];
    const float* W_dec = (const float*)d_in[4];
    const int*   nbna  = (const int*)d_in[5];
    float* out = (float*)d_out;
    float* out_topk  = out + 5;
    float* out_recon = out + 5 + (size_t)B_N * S_N;

    static int init_done = 0;
    static cudaStream_t s1;
    static cudaEvent_t eR, eS, eA;
    if (!init_done) {
        cudaFuncSetAttribute(enc_mma, cudaFuncAttributeMaxDynamicSharedMemorySize,
                             4 * 128 * ESTR * 2);
        cudaFuncSetAttribute(band_rank_kernel,
                             cudaFuncAttributeMaxDynamicSharedMemorySize,
                             BANDCAP * 12);
        int plo, phi;
        cudaDeviceGetStreamPriorityRange(&plo, &phi);
        cudaStreamCreateWithPriority(&s1, cudaStreamNonBlocking, phi);
        cudaEventCreateWithFlags(&eR, cudaEventDisableTiming);
        cudaEventCreateWithFlags(&eS, cudaEventDisableTiming);
        cudaEventCreateWithFlags(&eA, cudaEventDisableTiming);
        init_done = 1;
    }

    /* main: reset; fork prep chain onto s1 (overlaps sub/whl/enc) */
    reset_kernel<<<(S_N + 255) / 256, 256>>>(nbna);
    cudaEventRecord(eR, 0);
    cudaStreamWaitEvent(s1, eR, 0);
    dm1_kernel<<<30, 1024, 0, s1>>>();
    dm2_kernel<<<1, 1, 0, s1>>>();
    dm3_kernel<<<30, 1024, 0, s1>>>();
    zeroA_kernel<<<2048, 256, 0, s1>>>();
    wtT_kernel<<<dim3(S_N / 64, D_N / 64), 256, 0, s1>>>(W_dec);

    sub_kernel<<<B_N * D_N / 4 / 256, 256>>>(x, b_dec);
    whl_kernel<<<dim3(S_N / 64, D_N / 64), 256>>>(W_enc);
    enc_mma<<<dim3(B_N / 128, S_N / 128), 512, 4 * 128 * ESTR * 2>>>(b_enc);
    hist1_kernel<<<2048, 256>>>();
    scan1_kernel<<<1, 256>>>();
    l2hist_kernel<<<2048, 256>>>();
    scan2_kernel<<<1, 1>>>();
    scatter_kernel<<<2048, 256>>>(out_topk);
    cudaEventRecord(eS, 0);

    /* s1 (high prio): Ascatter + aux GEMM, overlapped with band/decode */
    cudaStreamWaitEvent(s1, eS, 0);
    Ascatter_kernel<<<B_N, 256, 0, s1>>>();
    aux_main<<<dim3(B_N / 128, D_N / 128), 256, 0, s1>>>();
    cudaEventRecord(eA, s1);

    band_dot_kernel<<<BANDCAP / 8, 256>>>(b_enc);
    band_rank_kernel<<<1, 1024, BANDCAP * 12>>>(out_topk);
    decode_kernel<<<B_N, 256>>>(x, b_dec, W_dec, out_recon);
    cudaStreamWaitEvent(0, eA, 0);
    aux_epi<<<B_N * D_N / 4 / 256, 256>>>(x);
    fin_kernel<<<1, 1>>>(out);
}

// round 17
// speedup vs baseline: 1.5764x; 1.0582x over previous
#include <cuda_runtime.h>
#include <cuda_bf16.h>
#include <cuda_fp16.h>
#include <cstdint>

#define B_N   2048
#define D_N   1024
#define S_N   30720
#define SN4   7680
#define NTHR  524288
#define KTOP  131072u
#define KAUX  2097152u
#define TOPCAP 160
#define BANDCAP 16384

/* ------------------------- scratch ------------------------- */
__device__ float g_acts[(size_t)B_N * S_N];
__device__ float g_xc[B_N * D_N];
__device__ float g_recon[B_N * D_N];
__device__ float g_D[B_N * D_N];                     /* aux GEMM result */
__device__ unsigned g_hist_a[4096];
__device__ unsigned g_hist_d[4096];
__device__ unsigned char g_dead[S_N];
__device__ int g_any_dead;
__device__ int g_b1a, g_b1d, g_b2a, g_b2d;
__device__ unsigned g_r1a, g_r1d;
__device__ unsigned g_tba, g_tbd;
__device__ unsigned g_hib, g_lob;
__device__ int g_bidx[BANDCAP];
__device__ float g_bhi[BANDCAP], g_blo[BANDCAP];
__device__ int g_nband, g_nhi;
__device__ unsigned short g_tcol[B_N * TOPCAP];
__device__ float          g_tval[B_N * TOPCAP];
__device__ int            g_tcnt[B_N];
__device__ double g_l2s[4];
__device__ double g_l1s;
__device__ unsigned long long g_l0s;
__device__ double g_auxs;

/* encoder fp16 GEMM scratch */
__device__ __half g_xhi[B_N * D_N];
__device__ __half g_Whi[(size_t)S_N * D_N];
__device__ float  g_WTe[(size_t)S_N * D_N];

/* dense aux GEMM scratch */
__device__ __nv_bfloat16 g_A[(size_t)B_N * S_N];
__device__ __nv_bfloat16 g_WT[(size_t)D_N * S_N];
__device__ int g_dmap[S_N];
__device__ int g_dinv[S_N];
__device__ int g_dcnt[32];
__device__ int g_ndead, g_ndead_pad;

/* ------------------------- exact f32 helpers ------------------------- */
__device__ __forceinline__ float fadd_rn(float a, float b) {
    float r; asm("add.rn.f32 %0, %1, %2;" : "=f"(r) : "f"(a), "f"(b)); return r;
}
__device__ __forceinline__ float fsub_rn(float a, float b) {
    float r; asm("sub.rn.f32 %0, %1, %2;" : "=f"(r) : "f"(a), "f"(b)); return r;
}
__device__ __forceinline__ float fmul_rn(float a, float b) {
    float r; asm("mul.rn.f32 %0, %1, %2;" : "=f"(r) : "f"(a), "f"(b)); return r;
}
__device__ __forceinline__ float ffma_rn(float a, float b, float c) {
    float r; asm("fma.rn.f32 %0, %1, %2, %3;" : "=f"(r) : "f"(a), "f"(b), "f"(c)); return r;
}

/* mma.sync bf16 / fp16 (baseline PTX, plain sm_103) */
__device__ __forceinline__ void mma_bf16(float* c, const unsigned* a, const unsigned* b) {
    asm volatile(
        "mma.sync.aligned.m16n8k16.row.col.f32.bf16.bf16.f32 "
        "{%0,%1,%2,%3}, {%4,%5,%6,%7}, {%8,%9}, {%0,%1,%2,%3};"
        : "+f"(c[0]), "+f"(c[1]), "+f"(c[2]), "+f"(c[3])
        : "r"(a[0]), "r"(a[1]), "r"(a[2]), "r"(a[3]), "r"(b[0]), "r"(b[1]));
}
__device__ __forceinline__ void mma_fp16(float* c, const unsigned* a, const unsigned* b) {
    asm volatile(
        "mma.sync.aligned.m16n8k16.row.col.f32.f16.f16.f32 "
        "{%0,%1,%2,%3}, {%4,%5,%6,%7}, {%8,%9}, {%0,%1,%2,%3};"
        : "+f"(c[0]), "+f"(c[1]), "+f"(c[2]), "+f"(c[3])
        : "r"(a[0]), "r"(a[1]), "r"(a[2]), "r"(a[3]), "r"(b[0]), "r"(b[1]));
}
__device__ __forceinline__ uint32_t smem_u32(const void* p) {
    uint32_t a;
    asm("{ .reg .u64 t; cvta.to.shared.u64 t, %1; cvt.u32.u64 %0, t; }"
        : "=r"(a) : "l"(p));
    return a;
}
__device__ __forceinline__ void ldm4(unsigned &r0, unsigned &r1,
                                     unsigned &r2, unsigned &r3, unsigned addr) {
    asm volatile("ldmatrix.sync.aligned.m8n8.x4.shared.b16 {%0,%1,%2,%3}, [%4];"
                 : "=r"(r0), "=r"(r1), "=r"(r2), "=r"(r3) : "r"(addr));
}
__device__ __forceinline__ void cp16(unsigned saddr, const void* gptr) {
    asm volatile("cp.async.cg.shared.global [%0], [%1], 16;"
                 :: "r"(saddr), "l"(gptr) : "memory");
}

/* ------------------------- setup ------------------------- */
__global__ void reset_kernel(const int* __restrict__ nbna) {
    int i = blockIdx.x * 256 + threadIdx.x;
    if (i == 0) {
        g_nband = 0; g_nhi = 0;
        g_l1s = 0.0; g_l0s = 0ull; g_auxs = 0.0; g_any_dead = 0;
        g_l2s[0] = g_l2s[1] = g_l2s[2] = g_l2s[3] = 0.0;
    }
    if (i < 4096) { g_hist_a[i] = 0; g_hist_d[i] = 0; }
    if (i < B_N) g_tcnt[i] = 0;
    if (i < S_N) {
        unsigned char d = (nbna[i] >= 20) ? 1 : 0;
        g_dead[i] = d;
        if (d) g_any_dead = 1;
    }
}

/* dead-feature dense mapping */
__global__ void dm1_kernel() {
    __shared__ int red[1024];
    int i = blockIdx.x * 1024 + threadIdx.x;
    red[threadIdx.x] = g_dead[i] ? 1 : 0;
    __syncthreads();
    for (int s = 512; s > 0; s >>= 1) {
        if (threadIdx.x < s) red[threadIdx.x] += red[threadIdx.x + s];
        __syncthreads();
    }
    if (threadIdx.x == 0) g_dcnt[blockIdx.x] = red[0];
}
__global__ void dm2_kernel() {
    int run = 0;
    for (int b = 0; b < 30; b++) {
        int c = g_dcnt[b];
        g_dcnt[b] = run;
        run += c;
    }
    g_ndead = run;
    g_ndead_pad = (run + 63) & ~63;
}
__global__ void dm3_kernel() {
    __shared__ int sc[1024];
    int i = blockIdx.x * 1024 + threadIdx.x;
    int f = g_dead[i] ? 1 : 0;
    sc[threadIdx.x] = f;
    __syncthreads();
    for (int off = 1; off < 1024; off <<= 1) {
        int v = (threadIdx.x >= off) ? sc[threadIdx.x - off] : 0;
        __syncthreads();
        sc[threadIdx.x] += v;
        __syncthreads();
    }
    if (f) {
        int dense = g_dcnt[blockIdx.x] + sc[threadIdx.x] - 1;
        g_dmap[i] = dense;
        g_dinv[dense] = i;
    }
}

/* W_dec^T (dead cols) bf16 tiled transpose */
__global__ void wtT_kernel(const float* __restrict__ W_dec) {
    __shared__ float tile[64][65];
    int pad = g_ndead_pad;
    int nd  = g_ndead;
    int j0 = blockIdx.x * 64;
    if (j0 >= pad) return;
    int d0 = blockIdx.y * 64;
    int t = threadIdx.x;
#pragma unroll
    for (int s = 0; s < 16; s++) {
        int idx = t + s * 256;
        int jl = idx >> 6, dl = idx & 63;
        int j = j0 + jl;
        float v = 0.f;
        if (j < nd) v = W_dec[(size_t)g_dinv[j] * D_N + d0 + dl];
        tile[jl][dl] = v;
    }
    __syncthreads();
#pragma unroll
    for (int s = 0; s < 16; s++) {
        int idx = t + s * 256;
        int dl = idx >> 6, jl = idx & 63;
        g_WT[(size_t)(d0 + dl) * pad + j0 + jl] = __float2bfloat16(tile[jl][dl]);
    }
}

/* W_enc transpose: [k][n] f32 -> [n][k] f32 exact + fp16 */
__global__ void whl_kernel(const float* __restrict__ W) {
    __shared__ float tile[64][65];
    int n0 = blockIdx.x * 64;
    int k0 = blockIdx.y * 64;
    int t = threadIdx.x;
#pragma unroll
    for (int s = 0; s < 16; s++) {
        int idx = t + s * 256;
        int kl = idx >> 6, nl = idx & 63;
        tile[kl][nl] = W[(size_t)(k0 + kl) * S_N + n0 + nl];
    }
    __syncthreads();
#pragma unroll
    for (int s = 0; s < 16; s++) {
        int idx = t + s * 256;
        int nl = idx >> 6, kl = idx & 63;
        float v = tile[kl][nl];
        g_WTe[(size_t)(n0 + nl) * D_N + k0 + kl] = v;
        g_Whi[(size_t)(n0 + nl) * D_N + k0 + kl] = __float2half_rn(v);
    }
}

/* build dense aux A directly from acts: A[row][j] = bf16(relu(acts - td)) */
__global__ void buildA_kernel() {
    int pad = g_ndead_pad;
    int nd  = g_ndead;
    const float td = __uint_as_float(g_tbd);
    size_t tot = (size_t)B_N * (size_t)pad;
    size_t stride = (size_t)gridDim.x * blockDim.x;
    for (size_t i = blockIdx.x * (size_t)blockDim.x + threadIdx.x; i < tot; i += stride) {
        int j = (int)(i % pad);
        int row = (int)(i / pad);
        float a = 0.f;
        if (j < nd) {
            float v = g_acts[(size_t)row * S_N + g_dinv[j]];
            float d = v - td;
            if (d > 0.f) a = d;
        }
        g_A[i] = __float2bfloat16(a);
    }
}

/* xc = x - b_dec  (f32 + fp16) */
__global__ void sub_kernel(const float* __restrict__ x,
                           const float* __restrict__ b_dec) {
    int i = blockIdx.x * 256 + threadIdx.x;
    float4 xv = ((const float4*)x)[i];
    float4 bv = ((const float4*)b_dec)[i & 255];
    float4 o;
    o.x = xv.x - bv.x; o.y = xv.y - bv.y;
    o.z = xv.z - bv.z; o.w = xv.w - bv.w;
    ((float4*)g_xc)[i] = o;
    ((__half2*)g_xhi)[i * 2]     = __floats2half2_rn(o.x, o.y);
    ((__half2*)g_xhi)[i * 2 + 1] = __floats2half2_rn(o.z, o.w);
}

/* ------------- encoder GEMM (fp16 mma.sync) ---------- */
#define EKCH 64
#define ESTR 72
__global__ __launch_bounds__(512) void enc_mma(const float* __restrict__ b_enc)
{
    extern __shared__ __half esm[];
    __half* sA = esm;
    __half* sB = esm + 2 * 128 * ESTR;

    const int tid = threadIdx.x;
    const int wid = tid >> 5, lane = tid & 31;
    const int warp_m = wid & 7;
    const int warp_n = wid >> 3;
    const int bm = blockIdx.x * 128;
    const int bn = blockIdx.y * 128;

    float acc[8][4];
#pragma unroll
    for (int nt = 0; nt < 8; nt++)
#pragma unroll
        for (int q = 0; q < 4; q++) acc[nt][q] = 0.f;

    const int lrow = tid >> 2;
    const int lcol = (tid & 3) * 16;

#define ELOAD(c, b) do {                                                     \
    int kof = (c) * EKCH + lcol;                                             \
    const __half* gA = &g_xhi[(size_t)(bm + lrow) * D_N + kof];              \
    const __half* gB = &g_Whi[(size_t)(bn + lrow) * D_N + kof];              \
    unsigned dA = smem_u32(sA + (b) * 128 * ESTR + lrow * ESTR + lcol);      \
    unsigned dB = smem_u32(sB + (b) * 128 * ESTR + lrow * ESTR + lcol);      \
    cp16(dA, gA); cp16(dA + 16, gA + 8);                                     \
    cp16(dB, gB); cp16(dB + 16, gB + 8);                                     \
    asm volatile("cp.async.commit_group;" ::: "memory");                     \
} while (0)

    ELOAD(0, 0);

    const int lr = (lane & 7) + (lane & 8);
    const int lc = (lane >> 4) << 3;

    for (int c = 0; c < 16; c++) {
        int buf = c & 1;
        if (c < 15) {
            ELOAD(c + 1, buf ^ 1);
            asm volatile("cp.async.wait_group 1;" ::: "memory");
        } else {
            asm volatile("cp.async.wait_group 0;" ::: "memory");
        }
        __syncthreads();
#pragma unroll
        for (int ks = 0; ks < 4; ks++) {
            int k0 = ks * 16;
            unsigned a[4];
            {
                unsigned addr = smem_u32(sA + buf * 128 * ESTR +
                                         (warp_m * 16 + lr) * ESTR + k0 + lc);
                ldm4(a[0], a[1], a[2], a[3], addr);
            }
            unsigned bb[8][2];
#pragma unroll
            for (int p = 0; p < 4; p++) {
                unsigned r0, r1, r2, r3;
                unsigned addr = smem_u32(sB + buf * 128 * ESTR +
                                         (warp_n * 64 + p * 16 + lr) * ESTR + k0 + lc);
                ldm4(r0, r1, r2, r3, addr);
                bb[2 * p][0] = r0; bb[2 * p + 1][0] = r1;
                bb[2 * p][1] = r2; bb[2 * p + 1][1] = r3;
            }
#pragma unroll
            for (int nt = 0; nt < 8; nt++)
                mma_fp16(acc[nt], a, bb[nt]);
        }
        __syncthreads();
    }

    const int crow = lane >> 2, ccol = (lane & 3) * 2;
    const int m1 = bm + warp_m * 16 + crow;
#pragma unroll
    for (int nt = 0; nt < 8; nt++) {
        int n = bn + warp_n * 64 + nt * 8 + ccol;
        float2 be = *(const float2*)&b_enc[n];
        float2 o1, o2;
        o1.x = fmaxf(acc[nt][0] + be.x, 0.f);
        o1.y = fmaxf(acc[nt][1] + be.y, 0.f);
        o2.x = fmaxf(acc[nt][2] + be.x, 0.f);
        o2.y = fmaxf(acc[nt][3] + be.y, 0.f);
        *(float2*)&g_acts[(size_t)m1 * S_N + n] = o1;
        *(float2*)&g_acts[(size_t)(m1 + 8) * S_N + n] = o2;
    }
}

/* ------------------------- level-1 histogram ------------------------- */
__global__ void hist1_kernel() {
    __shared__ unsigned ha[4096];
    __shared__ unsigned hd[4096];
    for (int i = threadIdx.x; i < 4096; i += 256) { ha[i] = 0; hd[i] = 0; }
    __syncthreads();
    int t = blockIdx.x * 256 + threadIdx.x;
    const float4* A4 = (const float4*)g_acts;
    for (int r = 0; r < 30; r++) {
        int i4 = t + r * NTHR;
        float4 v = A4[i4];
        int cb = (i4 % SN4) * 4;
        uchar4 dd = *(const uchar4*)&g_dead[cb];
        float vv[4] = {v.x, v.y, v.z, v.w};
        unsigned char dm[4] = {dd.x, dd.y, dd.z, dd.w};
#pragma unroll
        for (int j = 0; j < 4; j++) {
            if (vv[j] > 0.f) {
                unsigned bin = __float_as_uint(vv[j]) >> 20;
                atomicAdd(&ha[bin], 1u);
                if (dm[j]) atomicAdd(&hd[bin], 1u);
            }
        }
    }
    __syncthreads();
    for (int i = threadIdx.x; i < 4096; i += 256) {
        if (ha[i]) atomicAdd(&g_hist_a[i], ha[i]);
        if (hd[i]) atomicAdd(&g_hist_d[i], hd[i]);
    }
}

__global__ void scan1_kernel() {
    if (threadIdx.x == 0) {
        unsigned long long cum = 0;
        for (int b = 4095; b >= 0; b--) {
            cum += g_hist_a[b];
            if (cum >= (unsigned long long)KTOP) {
                g_b1a = b; g_r1a = KTOP - (unsigned)(cum - g_hist_a[b]); break;
            }
        }
        cum = 0;
        for (int b = 4095; b >= 0; b--) {
            cum += g_hist_d[b];
            if (cum >= (unsigned long long)KAUX) {
                g_b1d = b; g_r1d = KAUX - (unsigned)(cum - g_hist_d[b]); break;
            }
        }
    }
    __syncthreads();
    for (int i = threadIdx.x; i < 4096; i += 256) { g_hist_a[i] = 0; g_hist_d[i] = 0; }
}

/* ------------------- level-2 histogram fused (reads g_acts) ------------- */
__global__ void l2hist_kernel() {
    __shared__ unsigned ha[4096];
    __shared__ unsigned hd[4096];
    for (int i = threadIdx.x; i < 4096; i += 256) { ha[i] = 0; hd[i] = 0; }
    __syncthreads();
    int t = blockIdx.x * 256 + threadIdx.x;
    const unsigned b1a = (unsigned)g_b1a, b1d = (unsigned)g_b1d;
    const float4* A4 = (const float4*)g_acts;
    for (int r = 0; r < 30; r++) {
        int i4 = t + r * NTHR;
        float4 v = A4[i4];
        int cb = (i4 % SN4) * 4;
        uchar4 dd = *(const uchar4*)&g_dead[cb];
        float vv[4] = {v.x, v.y, v.z, v.w};
        unsigned char dm[4] = {dd.x, dd.y, dd.z, dd.w};
#pragma unroll
        for (int j = 0; j < 4; j++) {
            unsigned u = __float_as_uint(vv[j]);
            bool pos = vv[j] > 0.f;
            if (pos && ((u >> 20) == b1a)) atomicAdd(&ha[(u >> 8) & 0xFFF], 1u);
            if (pos && dm[j] && ((u >> 20) == b1d)) atomicAdd(&hd[(u >> 8) & 0xFFF], 1u);
        }
    }
    __syncthreads();
    for (int i = threadIdx.x; i < 4096; i += 256) {
        if (ha[i]) atomicAdd(&g_hist_a[i], ha[i]);
        if (hd[i]) atomicAdd(&g_hist_d[i], hd[i]);
    }
}

__global__ void scan2_kernel() {
    if (threadIdx.x == 0) {
        unsigned long long cum = 0; unsigned K = g_r1a;
        for (int b = 4095; b >= 0; b--) {
            cum += g_hist_a[b];
            if (cum >= (unsigned long long)K) { g_b2a = b; break; }
        }
        cum = 0; K = g_r1d;
        for (int b = 4095; b >= 0; b--) {
            cum += g_hist_d[b];
            if (cum >= (unsigned long long)K) { g_b2d = b; break; }
        }
        g_tba = ((unsigned)g_b1a << 20) | ((unsigned)g_b2a << 8);
        g_tbd = ((unsigned)g_b1d << 20) | ((unsigned)g_b2d << 8);
        float t = __uint_as_float(g_tba);
        g_hib = __float_as_uint(t * (1.0f + 3.2e-3f));
        g_lob = __float_as_uint(t * (1.0f - 3.0e-3f));
    }
}

/* ------------------------- candidate append helper ---------------------- */
__device__ __forceinline__ void wappend(unsigned* buf, int* ctr, unsigned cap,
                                        bool pred, unsigned val) {
    unsigned m = __ballot_sync(0xffffffffu, pred);
    if (!m) return;
    int lane = threadIdx.x & 31;
    int leader = __ffs(m) - 1;
    int base = 0;
    if (lane == leader) base = atomicAdd(ctr, __popc(m));
    base = __shfl_sync(0xffffffffu, base, leader);
    if (pred) {
        int pos = base + __popc(m & ((1u << lane) - 1u));
        if ((unsigned)pos < cap) buf[pos] = val;
    }
}

/* ------------------------- scatter (commit values) ---------------------- */
__global__ void scatter_kernel(float* __restrict__ outp) {
    __shared__ float redf[256];
    __shared__ int redi[256];
    const unsigned hib = g_hib;
    const unsigned lob = g_lob;
    int t = blockIdx.x * 256 + threadIdx.x;
    float l1loc = 0.f;
    int l0loc = 0;
#pragma unroll 4
    for (int r = 0; r < 120; r++) {
        int i = t + r * NTHR;
        float v = g_acts[i];
        int row = i / S_N;
        int col = i - row * S_N;
        unsigned u = __float_as_uint(v);
        bool pos = v > 0.f;
        bool keep = pos && (u > hib);
        outp[i] = keep ? v : 0.f;
        if (keep) {
            l1loc += v; l0loc++;
            int p = atomicAdd(&g_tcnt[row], 1);
            if (p < TOPCAP) {
                g_tcol[row * TOPCAP + p] = (unsigned short)col;
                g_tval[row * TOPCAP + p] = v;
            }
        }
        wappend((unsigned*)g_bidx, &g_nband, BANDCAP,
                pos && !keep && (u > lob), (unsigned)i);
    }
    redf[threadIdx.x] = l1loc;
    redi[threadIdx.x] = l0loc;
    __syncthreads();
    for (int s = 128; s > 0; s >>= 1) {
        if (threadIdx.x < s) {
            redf[threadIdx.x] += redf[threadIdx.x + s];
            redi[threadIdx.x] += redi[threadIdx.x + s];
        }
        __syncthreads();
    }
    if (threadIdx.x == 0) {
        atomicAdd(&g_l1s, (double)redf[0]);
        atomicAdd(&g_l0s, (unsigned long long)redi[0]);
        atomicAdd(&g_nhi, redi[0]);
    }
}

/* ------------------------- exact dot (double-f32, coalesced WTe) -------- */
__device__ __forceinline__ void exact_dot(int row, int col, int lane,
                                          float& sh_out, float& sl_out) {
    const float* xr = &g_xc[row * D_N];
    const float* wr = &g_WTe[(size_t)col * D_N];
    float sh = 0.f, sl = 0.f;
#pragma unroll 4
    for (int j = 0; j < 32; j++) {
        int k = lane + j * 32;
        float a = xr[k], b = wr[k];
        float ph = fmul_rn(a, b);
        float pl = ffma_rn(a, b, -ph);
        float s  = fadd_rn(sh, ph);
        float bb = fsub_rn(s, sh);
        float e1 = fsub_rn(sh, fsub_rn(s, bb));
        float e2 = fsub_rn(ph, bb);
        sh = s;
        sl = fadd_rn(sl, fadd_rn(fadd_rn(e1, e2), pl));
    }
    for (int off = 16; off; off >>= 1) {
        float oh = __shfl_down_sync(0xffffffffu, sh, off);
        float ol = __shfl_down_sync(0xffffffffu, sl, off);
        float s  = fadd_rn(sh, oh);
        float bb = fsub_rn(s, sh);
        float e1 = fsub_rn(sh, fsub_rn(s, bb));
        float e2 = fsub_rn(oh, bb);
        sh = s;
        sl = fadd_rn(sl, fadd_rn(fadd_rn(e1, e2), ol));
    }
    sh_out = sh; sl_out = sl;
}

/* exact band dots */
__global__ void band_dot_kernel(const float* __restrict__ b_enc) {
    int w = (blockIdx.x * 256 + threadIdx.x) >> 5;
    int lane = threadIdx.x & 31;
    int nb = min(g_nband, (int)BANDCAP);
    if (w >= nb) return;
    int idx = g_bidx[w];
    int row = idx / S_N, col = idx - row * S_N;
    float sh, sl;
    exact_dot(row, col, lane, sh, sl);
    if (lane == 0) {
        double val = (double)sh + (double)sl + (double)b_enc[col];
        float hh = (float)val;
        g_bhi[w] = hh;
        g_blo[w] = (float)(val - (double)hh);
    }
}

/* ------------------------- band ranking + commit (adaptive bitonic) ----- */
__global__ __launch_bounds__(1024) void band_rank_kernel(float* __restrict__ outp) {
    extern __shared__ char bsm[];
    double* sval = (double*)bsm;
    int*    sidx = (int*)(bsm + (size_t)BANDCAP * 8);
    __shared__ double rsm[32];
    int tid = threadIdx.x;
    int nb = min(g_nband, (int)BANDCAP);
    int nb2 = 2048;
    while (nb2 < nb) nb2 <<= 1;
    for (int i = tid; i < nb2; i += 1024) {
        if (i < nb) {
            sval[i] = (double)g_bhi[i] + (double)g_blo[i];
            sidx[i] = g_bidx[i];
        } else {
            sval[i] = -1e300;
            sidx[i] = 0x7fffffff;
        }
    }
    __syncthreads();
    for (int size = 2; size <= nb2; size <<= 1) {
        for (int stride = size >> 1; stride; stride >>= 1) {
            for (int i = tid; i < nb2 / 2; i += 1024) {
                int pos = 2 * i - (i & (stride - 1));
                int a = pos, b = pos + stride;
                bool dirDesc = ((pos & size) == 0);
                bool agtb = (sval[a] != sval[b]) ? (sval[a] > sval[b])
                                                 : (sidx[a] < sidx[b]);
                if (dirDesc ? !agtb : agtb) {
                    double tv = sval[a]; sval[a] = sval[b]; sval[b] = tv;
                    int ti = sidx[a]; sidx[a] = sidx[b]; sidx[b] = ti;
                }
            }
            __syncthreads();
        }
    }
    int needK = (int)KTOP - g_nhi;
    if (needK < 0) needK = 0;
    if (needK > nb) needK = nb;
    double l1loc = 0.0;
    for (int i = tid; i < needK; i += 1024) {
        int idx = sidx[i];
        float fv = (float)sval[i];
        outp[idx] = fv;
        int row = idx / S_N, col = idx - row * S_N;
        int p = atomicAdd(&g_tcnt[row], 1);
        if (p < TOPCAP) {
            g_tcol[row * TOPCAP + p] = (unsigned short)col;
            g_tval[row * TOPCAP + p] = fv;
        }
        l1loc += (double)fv;
    }
    for (int off = 16; off; off >>= 1)
        l1loc += __shfl_down_sync(0xffffffffu, l1loc, off);
    if ((tid & 31) == 0) rsm[tid >> 5] = l1loc;
    __syncthreads();
    if (tid == 0) {
        double s = 0.0;
        for (int q = 0; q < 32; q++) s += rsm[q];
        atomicAdd(&g_l1s, s);
        atomicAdd(&g_l0s, (unsigned long long)needK);
    }
}

/* ------------------------- sparse Matryoshka decode ------------------------- */
__global__ void decode_kernel(const float* __restrict__ x,
                              const float* __restrict__ b_dec,
                              const float* __restrict__ W_dec,
                              float* __restrict__ out_recon)
{
    __shared__ unsigned short scol[TOPCAP];
    __shared__ float sval[TOPCAP];
    __shared__ float red[256];
    int row = blockIdx.x, tid = threadIdx.x;
    int cnt = min(g_tcnt[row], TOPCAP);
    for (int i = tid; i < cnt; i += 256) {
        scol[i] = g_tcol[row * TOPCAP + i];
        sval[i] = g_tval[row * TOPCAP + i];
    }
    __syncthreads();
    int d = tid * 4;
    float4 acc = *(const float4*)&b_dec[d];
    float4 xv = *(const float4*)&x[row * D_N + d];
    const int bounds[5] = {0, 2048, 6144, 14336, 30720};
#pragma unroll
    for (int g = 0; g < 4; g++) {
        int lo = bounds[g], hi = bounds[g + 1];
        for (int e = 0; e < cnt; e++) {
            int c = scol[e];
            if (c >= lo && c < hi) {
                float vv = sval[e];
                float4 w = *(const float4*)&W_dec[(size_t)c * D_N + d];
                acc.x += vv * w.x; acc.y += vv * w.y;
                acc.z += vv * w.z; acc.w += vv * w.w;
            }
        }
        float dx = acc.x - xv.x, dy = acc.y - xv.y;
        float dz = acc.z - xv.z, dw = acc.w - xv.w;
        red[tid] = dx * dx + dy * dy + dz * dz + dw * dw;
        __syncthreads();
        for (int s = 128; s > 0; s >>= 1) {
            if (tid < s) red[tid] += red[tid + s];
            __syncthreads();
        }
        if (tid == 0) atomicAdd(&g_l2s[g], (double)red[0]);
        __syncthreads();
    }
    float* ro = out_recon + (size_t)row * D_N + d;
    ro[0] = acc.x; ro[1] = acc.y; ro[2] = acc.z; ro[3] = acc.w;
    *(float4*)&g_recon[row * D_N + d] = acc;
}

/* ----------------- aux dense GEMM mainloop (stores D) ------------------- */
#define KCH 32
#define SSTR 40
__global__ __launch_bounds__(256) void aux_main()
{
    __shared__ __align__(16) __nv_bfloat16 sA[2][128][SSTR];
    __shared__ __align__(16) __nv_bfloat16 sB[2][128][SSTR];

    if (g_ndead == 0) return;
    const int pad = g_ndead_pad;
    const int nchunks = pad / KCH;
    const int tid = threadIdx.x;
    const int wid = tid >> 5;
    const int lane = tid & 31;
    const int warp_m = wid & 3;
    const int warp_n = wid >> 2;
    const int bm = blockIdx.x * 128;
    const int bn = blockIdx.y * 128;
    const int m0 = bm + warp_m * 32;
    const int n0l = warp_n * 64;

    float acc[2][8][4];
#pragma unroll
    for (int mt = 0; mt < 2; mt++)
#pragma unroll
        for (int nt = 0; nt < 8; nt++)
#pragma unroll
            for (int q = 0; q < 4; q++) acc[mt][nt][q] = 0.f;

    const int lrow = tid >> 1;
    const int lseg = tid & 1;

#define LOAD_CHUNK(c, b)                                                        \
    do {                                                                        \
        int kof = (c) * KCH;                                                    \
        cp16(smem_u32(&sA[b][lrow][(lseg) * 8]),                                \
             &g_A[(size_t)(bm + lrow) * pad + kof + (lseg) * 8]);               \
        cp16(smem_u32(&sA[b][lrow][(lseg + 2) * 8]),                            \
             &g_A[(size_t)(bm + lrow) * pad + kof + (lseg + 2) * 8]);           \
        cp16(smem_u32(&sB[b][lrow][(lseg) * 8]),                                \
             &g_WT[(size_t)(bn + lrow) * pad + kof + (lseg) * 8]);              \
        cp16(smem_u32(&sB[b][lrow][(lseg + 2) * 8]),                            \
             &g_WT[(size_t)(bn + lrow) * pad + kof + (lseg + 2) * 8]);          \
        asm volatile("cp.async.commit_group;" ::: "memory");                    \
    } while (0)

    LOAD_CHUNK(0, 0);

    const int lr = (lane & 7) + (lane & 8);
    const int lc = (lane >> 4) << 3;

    for (int c = 0; c < nchunks; c++) {
        int buf = c & 1;
        if (c + 1 < nchunks) {
            LOAD_CHUNK(c + 1, (c + 1) & 1);
            asm volatile("cp.async.wait_group 1;" ::: "memory");
        } else {
            asm volatile("cp.async.wait_group 0;" ::: "memory");
        }
        __syncthreads();

#pragma unroll
        for (int ks = 0; ks < KCH / 16; ks++) {
            int k0 = ks * 16;
            unsigned a[2][4];
#pragma unroll
            for (int mt = 0; mt < 2; mt++) {
                unsigned addr = smem_u32(&sA[buf][warp_m * 32 + mt * 16 + lr][k0 + lc]);
                ldm4(a[mt][0], a[mt][1], a[mt][2], a[mt][3], addr);
            }
            unsigned bb[8][2];
#pragma unroll
            for (int p = 0; p < 4; p++) {
                unsigned r0, r1, r2, r3;
                unsigned addr = smem_u32(&sB[buf][n0l + p * 16 + lr][k0 + lc]);
                ldm4(r0, r1, r2, r3, addr);
                bb[2 * p][0] = r0; bb[2 * p + 1][0] = r1;
                bb[2 * p][1] = r2; bb[2 * p + 1][1] = r3;
            }
#pragma unroll
            for (int mt = 0; mt < 2; mt++)
#pragma unroll
                for (int nt = 0; nt < 8; nt++)
                    mma_bf16(acc[mt][nt], a[mt], bb[nt]);
        }
        __syncthreads();
    }

    const int crow = lane >> 2;
    const int ccol = (lane & 3) * 2;
    const int n0 = bn + n0l;
#pragma unroll
    for (int mt = 0; mt < 2; mt++) {
#pragma unroll
        for (int nt = 0; nt < 8; nt++) {
            int m1 = m0 + mt * 16 + crow;
            int m2 = m1 + 8;
            int dd = n0 + nt * 8 + ccol;
            float2 v1 = {acc[mt][nt][0], acc[mt][nt][1]};
            float2 v2 = {acc[mt][nt][2], acc[mt][nt][3]};
            *(float2*)&g_D[(size_t)m1 * D_N + dd] = v1;
            *(float2*)&g_D[(size_t)m2 * D_N + dd] = v2;
        }
    }
}

/* ----------------- aux loss epilogue (needs recon) ----------------------- */
__global__ void aux_epi(const float* __restrict__ x) {
    __shared__ float red[256];
    if (g_ndead == 0) return;
    int i = blockIdx.x * 256 + threadIdx.x;
    float4 dv = ((const float4*)g_D)[i];
    float4 xv = ((const float4*)x)[i];
    float4 rv = ((const float4*)g_recon)[i];
    float d0 = dv.x - (xv.x - rv.x);
    float d1 = dv.y - (xv.y - rv.y);
    float d2 = dv.z - (xv.z - rv.z);
    float d3 = dv.w - (xv.w - rv.w);
    red[threadIdx.x] = d0 * d0 + d1 * d1 + d2 * d2 + d3 * d3;
    __syncthreads();
    for (int s = 128; s > 0; s >>= 1) {
        if (threadIdx.x < s) red[threadIdx.x] += red[threadIdx.x + s];
        __syncthreads();
    }
    if (threadIdx.x == 0) atomicAdd(&g_auxs, (double)red[0]);
}

/* ------------------------- finalize ------------------------- */
__global__ void fin_kernel(float* __restrict__ out) {
    double inv = 1.0 / ((double)B_N * (double)D_N);
    double l2m = (g_l2s[0] + g_l2s[1] + g_l2s[2] + g_l2s[3]) * 0.25 * inv;
    double l1 = 1e-3 * g_l1s / (double)B_N;
    double l0 = (double)g_l0s / (double)B_N;
    double aux = g_any_dead ? (1e-2 * g_auxs * inv) : 0.0;
    out[0] = (float)(l2m + l1 + aux);
    out[1] = (float)l2m;
    out[2] = (float)l1;
    out[3] = (float)aux;
    out[4] = (float)l0;
}

/* ------------------------- launch ------------------------- */
extern "C" void kernel_launch(void* const* d_in, const int* in_sizes, int n_in,
                              void* d_out, int out_size) {
    const float* x     = (const float*)d_in[0];
    const float* b_dec = (const float*)d_in[1];
    const float* b_enc = (const float*)d_in[2];
    const float* W_enc = (const float*)d_in[3];
    const float* W_dec = (const float*)d_in[4];
    const int*   nbna  = (const int*)d_in[5];
    float* out = (float*)d_out;
    float* out_topk  = out + 5;
    float* out_recon = out + 5 + (size_t)B_N * S_N;

    static int init_done = 0;
    static cudaStream_t s1;
    static cudaEvent_t eR, eT, eA;
    if (!init_done) {
        cudaFuncSetAttribute(enc_mma, cudaFuncAttributeMaxDynamicSharedMemorySize,
                             4 * 128 * ESTR * 2);
        cudaFuncSetAttribute(band_rank_kernel,
                             cudaFuncAttributeMaxDynamicSharedMemorySize,
                             BANDCAP * 12);
        int plo, phi;
        cudaDeviceGetStreamPriorityRange(&plo, &phi);
        cudaStreamCreateWithPriority(&s1, cudaStreamNonBlocking, phi);
        cudaEventCreateWithFlags(&eR, cudaEventDisableTiming);
        cudaEventCreateWithFlags(&eT, cudaEventDisableTiming);
        cudaEventCreateWithFlags(&eA, cudaEventDisableTiming);
        init_done = 1;
    }

    /* main: reset; fork prep chain onto s1 (overlaps sub/whl/enc) */
    reset_kernel<<<(S_N + 255) / 256, 256>>>(nbna);
    cudaEventRecord(eR, 0);
    cudaStreamWaitEvent(s1, eR, 0);
    dm1_kernel<<<30, 1024, 0, s1>>>();
    dm2_kernel<<<1, 1, 0, s1>>>();
    dm3_kernel<<<30, 1024, 0, s1>>>();
    wtT_kernel<<<dim3(S_N / 64, D_N / 64), 256, 0, s1>>>(W_dec);

    sub_kernel<<<B_N * D_N / 4 / 256, 256>>>(x, b_dec);
    whl_kernel<<<dim3(S_N / 64, D_N / 64), 256>>>(W_enc);
    enc_mma<<<dim3(B_N / 128, S_N / 128), 512, 4 * 128 * ESTR * 2>>>(b_enc);
    hist1_kernel<<<2048, 256>>>();
    scan1_kernel<<<1, 256>>>();
    l2hist_kernel<<<2048, 256>>>();
    scan2_kernel<<<1, 1>>>();
    cudaEventRecord(eT, 0);

    /* s1 (high prio): buildA + aux GEMM, overlapped with scatter/band/decode */
    cudaStreamWaitEvent(s1, eT, 0);
    buildA_kernel<<<2048, 256, 0, s1>>>();
    aux_main<<<dim3(B_N / 128, D_N / 128), 256, 0, s1>>>();
    cudaEventRecord(eA, s1);

    scatter_kernel<<<2048, 256>>>(out_topk);
    band_dot_kernel<<<BANDCAP / 8, 256>>>(b_enc);
    band_rank_kernel<<<1, 1024, BANDCAP * 12>>>(out_topk);
    decode_kernel<<<B_N, 256>>>(x, b_dec, W_dec, out_recon);
    cudaStreamWaitEvent(0, eA, 0);
    aux_epi<<<B_N * D_N / 4 / 256, 256>>>(x);
    fin_kernel<<<1, 1>>>(out);
}